// round 5
// baseline (speedup 1.0000x reference)
#include <cuda_runtime.h>
#include <cstdint>

#define THREADS  128        // 4 warps: warp grid 1m x 4n, warp tile 64x64
#define PTHREADS 256
#define TM       64         // batch rows per CTA
#define HID      256
#define INP      128
#define CAT      384
#define NCH      48         // K chunks of 8
#define CHW      2048       // words per chunk (256 n x 8 k)
#define CHB      8192       // bytes per chunk

// Pre-converted (tf32, pair-interleaved) weights: [Wz | Wr | Wh], each NCH*CHW words.
// chunk layout: word = n*8 + p, p = 2*(kl&3) + (kl>>2), kl = k - chunk*8
__device__ uint32_t wscratch[3 * NCH * CHW];

static __device__ __forceinline__ uint32_t smem_u32(const void* p) {
    uint32_t a;
    asm("{ .reg .u64 t; cvta.to.shared.u64 t, %1; cvt.u32.u64 %0, t; }" : "=r"(a) : "l"(p));
    return a;
}
static __device__ __forceinline__ uint64_t gptr(const void* p) {
    uint64_t r;
    asm("cvta.to.global.u64 %0, %1;" : "=l"(r) : "l"(p));
    return r;
}
static __device__ __forceinline__ uint32_t f2tf32(float v) {
    uint32_t t;
    asm("cvt.rna.tf32.f32 %0, %1;" : "=r"(t) : "f"(v));
    return t;
}
// A smem word offset for (row r, k): pair-interleaved within 8-groups + XOR swizzle
static __device__ __forceinline__ int a_off(int r, int k) {
    int g = k >> 3, kl = k & 7;
    int p = 2 * (kl & 3) + (kl >> 2);
    return r * CAT + ((g * 8 + p) ^ ((r & 3) << 3));
}
static __device__ __forceinline__ void mma8(float* d, uint32_t a0, uint32_t a1,
                                            uint32_t a2, uint32_t a3,
                                            uint32_t b0, uint32_t b1) {
    asm volatile(
        "mma.sync.aligned.m16n8k8.row.col.f32.tf32.tf32.f32 "
        "{%0,%1,%2,%3}, {%4,%5,%6,%7}, {%8,%9}, {%0,%1,%2,%3};"
        : "+f"(d[0]), "+f"(d[1]), "+f"(d[2]), "+f"(d[3])
        : "r"(a0), "r"(a1), "r"(a2), "r"(a3), "r"(b0), "r"(b1));
}
static __device__ __forceinline__ void cpa16(uint32_t saddr, uint64_t gaddr) {
    asm volatile("cp.async.ca.shared.global [%0], [%1], 16;" :: "r"(saddr), "l"(gaddr) : "memory");
}
#define CP_COMMIT() asm volatile("cp.async.commit_group;" ::: "memory")
#define CP_WAIT(n)  asm volatile("cp.async.wait_group %0;" :: "n"(n) : "memory")

// load one 8KB chunk: 4 x 16B per thread (128 threads)
static __device__ __forceinline__ void load_chunk(uint32_t sdst, uint64_t gsrc, int tid) {
    #pragma unroll
    for (int u = 0; u < 4; u++)
        cpa16(sdst + tid * 64 + u * 16, gsrc + (size_t)tid * 64 + u * 16);
    CP_COMMIT();
}

// ---------------- weight pre-conversion: fp32 -> tf32, pair-interleaved chunk image -----
__global__ void preconv_kernel(const float* __restrict__ Wz, const float* __restrict__ Wr,
                               const float* __restrict__ Wh) {
    int gid = blockIdx.x * PTHREADS + threadIdx.x;
    if (gid >= 3 * NCH * CHW) return;
    int w = gid / (NCH * CHW);
    int rem = gid - w * (NCH * CHW);
    int c = rem >> 11;            // / 2048
    int widx = rem & 2047;
    int n = widx >> 3;
    int p = widx & 7;
    int kl = (p >> 1) + ((p & 1) << 2);
    int k = c * 8 + kl;
    const float* W = (w == 0) ? Wz : (w == 1) ? Wr : Wh;
    wscratch[gid] = f2tf32(W[(size_t)n * CAT + k]);
}

// ---------------- one K=384 GEMM pass: CTA tile 64x256, warp tile 64x64 -----------------
static __device__ __forceinline__ void gemm_pass(
    const uint32_t* Asu, const uint32_t* Bsu, uint32_t bs_byte,
    const uint32_t* wbase, float (&acc)[4][8][4],
    int n0, int lane, int tid)
{
    #pragma unroll
    for (int mt = 0; mt < 4; mt++)
        #pragma unroll
        for (int nt = 0; nt < 8; nt++)
            #pragma unroll
            for (int q = 0; q < 4; q++) acc[mt][nt][q] = 0.f;

    uint64_t g0 = gptr(wbase);
    load_chunk(bs_byte, g0, tid);

    const int rq = lane >> 2;       // 0..7
    const int kq = lane & 3;        // 0..3

    #pragma unroll 1
    for (int c = 0; c < NCH; c++) {
        if (c + 1 < NCH) {
            load_chunk(bs_byte + ((c + 1) & 1) * CHB, g0 + (size_t)(c + 1) * CHB, tid);
            CP_WAIT(1);
        } else {
            CP_WAIT(0);
        }
        __syncthreads();

        const uint32_t* B = Bsu + (c & 1) * CHW;
        // B fragments: LDS.64 gives (k=kq, k=kq+4) for column n
        uint32_t bf[8][2];
        #pragma unroll
        for (int nt = 0; nt < 8; nt++) {
            int n = n0 + nt * 8 + rq;
            uint2 v = *reinterpret_cast<const uint2*>(B + n * 8 + 2 * kq);
            bf[nt][0] = v.x; bf[nt][1] = v.y;
        }
        #pragma unroll
        for (int mt = 0; mt < 4; mt++) {
            int r = mt * 16 + rq;
            int xr = (r & 3) << 3;                      // (r+8)&3 == r&3
            uint2 lo = *reinterpret_cast<const uint2*>(Asu + r * CAT + ((c * 8 + 2 * kq) ^ xr));
            uint2 hi = *reinterpret_cast<const uint2*>(Asu + (r + 8) * CAT + ((c * 8 + 2 * kq) ^ xr));
            #pragma unroll
            for (int nt = 0; nt < 8; nt++)
                mma8(acc[mt][nt], lo.x, hi.x, lo.y, hi.y, bf[nt][0], bf[nt][1]);
        }
        __syncthreads();
    }
}

// ---------------- fused GRU kernel ------------------------------------------------------
__global__ void __launch_bounds__(THREADS, 2) gru_main_kernel(
    const float* __restrict__ x, const float* __restrict__ hp,
    const float* __restrict__ bz, const float* __restrict__ br,
    const float* __restrict__ bh, float* __restrict__ out)
{
    extern __shared__ uint32_t sm[];
    uint32_t* Asu = sm;                       // 64*384 words (tf32 ih, interleave+swizzle)
    uint32_t* Bsu = sm + TM * CAT;            // 2 * 2048 words (B double buffer)
    const uint32_t bs_byte = smem_u32(Bsu);

    const int tid  = threadIdx.x;
    const int lane = tid & 31;
    const int warp = tid >> 5;
    const int n0   = warp * 64;
    const int blockRow = blockIdx.x * TM;

    // ---- fill A smem: tf32(ih); thread handles one 8-k group per iter ----
    #pragma unroll 1
    for (int it = 0; it < 24; it++) {
        int idx = it * THREADS + tid;          // 0 .. 3071 groups
        int row = idx / 48;
        int g8  = idx - row * 48;
        int k0  = g8 * 8;
        const float* src = (k0 < INP) ? (x + (size_t)(blockRow + row) * INP + k0)
                                      : (hp + (size_t)(blockRow + row) * HID + (k0 - INP));
        float4 v0 = *reinterpret_cast<const float4*>(src);
        float4 v1 = *reinterpret_cast<const float4*>(src + 4);
        uint4 u0, u1;   // positions [k0,k4,k1,k5] and [k2,k6,k3,k7]
        u0.x = f2tf32(v0.x); u0.y = f2tf32(v1.x); u0.z = f2tf32(v0.y); u0.w = f2tf32(v1.y);
        u1.x = f2tf32(v0.z); u1.y = f2tf32(v1.z); u1.z = f2tf32(v0.w); u1.w = f2tf32(v1.w);
        int base = row * CAT + ((g8 * 8) ^ ((row & 3) << 3));
        *reinterpret_cast<uint4*>(Asu + base)     = u0;
        *reinterpret_cast<uint4*>(Asu + base + 4) = u1;
    }
    __syncthreads();

    float acc[4][8][4];

    // ================= pass 1: z = hardsigmoid(ih @ Wz^T + bz) -> out (scratch) =========
    gemm_pass(Asu, Bsu, bs_byte, wscratch, acc, n0, lane, tid);
    #pragma unroll
    for (int mt = 0; mt < 4; mt++) {
        int rl = mt * 16 + (lane >> 2);
        #pragma unroll
        for (int nt = 0; nt < 8; nt++) {
            int cb = n0 + nt * 8 + ((lane & 3) << 1);
            float2 bv = *reinterpret_cast<const float2*>(bz + cb);
            float z0 = __saturatef((acc[mt][nt][0] + bv.x) * 0.16666667f + 0.5f);
            float z1 = __saturatef((acc[mt][nt][1] + bv.y) * 0.16666667f + 0.5f);
            float z2 = __saturatef((acc[mt][nt][2] + bv.x) * 0.16666667f + 0.5f);
            float z3 = __saturatef((acc[mt][nt][3] + bv.y) * 0.16666667f + 0.5f);
            size_t o0 = (size_t)(blockRow + rl) * HID + cb;
            size_t o1 = (size_t)(blockRow + rl + 8) * HID + cb;
            *reinterpret_cast<float2*>(out + o0) = make_float2(z0, z1);
            *reinterpret_cast<float2*>(out + o1) = make_float2(z2, z3);
        }
    }

    // ================= pass 2: r = hardsigmoid(ih @ Wr^T + br); A_h := tf32(r * h) ======
    gemm_pass(Asu, Bsu, bs_byte, wscratch + NCH * CHW, acc, n0, lane, tid);
    // gemm_pass ends with __syncthreads(): all warps done reading A; safe to rewrite.
    const float* Asf = reinterpret_cast<const float*>(Asu);
    #pragma unroll
    for (int mt = 0; mt < 4; mt++) {
        int rl = mt * 16 + (lane >> 2);
        #pragma unroll
        for (int nt = 0; nt < 8; nt++) {
            int cb = n0 + nt * 8 + ((lane & 3) << 1);
            float2 bv = *reinterpret_cast<const float2*>(br + cb);
            float r0 = __saturatef((acc[mt][nt][0] + bv.x) * 0.16666667f + 0.5f);
            float r1 = __saturatef((acc[mt][nt][1] + bv.y) * 0.16666667f + 0.5f);
            float r2 = __saturatef((acc[mt][nt][2] + bv.x) * 0.16666667f + 0.5f);
            float r3 = __saturatef((acc[mt][nt][3] + bv.y) * 0.16666667f + 0.5f);
            int kA = INP + cb;
            int o00 = a_off(rl, kA),     o01 = a_off(rl, kA + 1);
            int o10 = a_off(rl + 8, kA), o11 = a_off(rl + 8, kA + 1);
            Asu[o00] = f2tf32(r0 * Asf[o00]);
            Asu[o01] = f2tf32(r1 * Asf[o01]);
            Asu[o10] = f2tf32(r2 * Asf[o10]);
            Asu[o11] = f2tf32(r3 * Asf[o11]);
        }
    }
    __syncthreads();

    // ================= pass 3: htilde; h_next = z*h + (1-z)*hardtanh(.) =================
    gemm_pass(Asu, Bsu, bs_byte, wscratch + 2 * NCH * CHW, acc, n0, lane, tid);
    #pragma unroll
    for (int mt = 0; mt < 4; mt++) {
        int rl = mt * 16 + (lane >> 2);
        #pragma unroll
        for (int nt = 0; nt < 8; nt++) {
            int cb = n0 + nt * 8 + ((lane & 3) << 1);
            float2 bv = *reinterpret_cast<const float2*>(bh + cb);
            size_t o0 = (size_t)(blockRow + rl) * HID + cb;
            size_t o1 = (size_t)(blockRow + rl + 8) * HID + cb;
            float2 zz0 = *reinterpret_cast<const float2*>(out + o0);  // z written by this thread
            float2 zz1 = *reinterpret_cast<const float2*>(out + o1);
            float2 hh0 = *reinterpret_cast<const float2*>(hp + o0);
            float2 hh1 = *reinterpret_cast<const float2*>(hp + o1);
            float t0 = fminf(fmaxf(acc[mt][nt][0] + bv.x, -1.f), 1.f);
            float t1 = fminf(fmaxf(acc[mt][nt][1] + bv.y, -1.f), 1.f);
            float t2 = fminf(fmaxf(acc[mt][nt][2] + bv.x, -1.f), 1.f);
            float t3 = fminf(fmaxf(acc[mt][nt][3] + bv.y, -1.f), 1.f);
            float2 r0, r1;
            r0.x = zz0.x * hh0.x + (1.f - zz0.x) * t0;
            r0.y = zz0.y * hh0.y + (1.f - zz0.y) * t1;
            r1.x = zz1.x * hh1.x + (1.f - zz1.x) * t2;
            r1.y = zz1.y * hh1.y + (1.f - zz1.y) * t3;
            *reinterpret_cast<float2*>(out + o0) = r0;
            *reinterpret_cast<float2*>(out + o1) = r1;
        }
    }
}

extern "C" void kernel_launch(void* const* d_in, const int* in_sizes, int n_in,
                              void* d_out, int out_size) {
    const float* x  = (const float*)d_in[0];
    const float* hp = (const float*)d_in[1];
    const float* Wz = (const float*)d_in[2];
    const float* bz = (const float*)d_in[3];
    const float* Wr = (const float*)d_in[4];
    const float* br = (const float*)d_in[5];
    const float* Wh = (const float*)d_in[6];
    const float* bh = (const float*)d_in[7];
    float* out = (float*)d_out;

    preconv_kernel<<<(3 * NCH * CHW + PTHREADS - 1) / PTHREADS, PTHREADS>>>(Wz, Wr, Wh);

    int batch = in_sizes[0] / INP;
    int grid = batch / TM;
    size_t smem = (size_t)(TM * CAT + 2 * CHW) * 4;   // 114688 B = 112 KB
    cudaFuncSetAttribute(gru_main_kernel,
                         cudaFuncAttributeMaxDynamicSharedMemorySize, (int)smem);
    gru_main_kernel<<<grid, THREADS, smem>>>(x, hp, bz, br, bh, out);
}

// round 6
// speedup vs baseline: 1.7822x; 1.7822x over previous
#include <cuda_runtime.h>
#include <cuda_fp16.h>
#include <cstdint>

#define THREADS  256        // 8 warps: warp grid 2m x 4n, warp tile 32x64
#define TM       64         // batch rows per CTA
#define HID      256
#define INP      128
#define CAT      384
#define NCH      24         // K chunks of 16 (one 16-k group per chunk)
#define CHW      2048       // uint32 words per chunk (256 n x 8 words)
#define CHB      8192       // bytes per chunk
#define STAGES   4
#define AROWW    192        // words per A row (384 fp16)

// Pre-converted (fp16, pair-interleaved) weights: [Wz | Wr | Wh], each NCH*CHW words.
// word layout per (chunk c, row n): pos p (0..7) holds k-pair j = (p>>1) + (p&1)*4,
// i.e. fp16x2 of (k, k+1) with k = c*16 + 2*j.
__device__ uint32_t wscratch[3 * NCH * CHW];

static __device__ __forceinline__ uint64_t gptr(const void* p) {
    uint64_t r;
    asm("cvta.to.global.u64 %0, %1;" : "=l"(r) : "l"(p));
    return r;
}
static __device__ __forceinline__ uint32_t smem_u32(const void* p) {
    uint32_t a;
    asm("{ .reg .u64 t; cvta.to.shared.u64 t, %1; cvt.u32.u64 %0, t; }" : "=r"(a) : "l"(p));
    return a;
}
static __device__ __forceinline__ uint32_t h2pack(float a, float b) {
    __half2 h = __floats2half2_rn(a, b);
    return *reinterpret_cast<uint32_t*>(&h);
}
static __device__ __forceinline__ void mma16(float* d, uint32_t a0, uint32_t a1,
                                             uint32_t a2, uint32_t a3,
                                             uint32_t b0, uint32_t b1) {
    asm volatile(
        "mma.sync.aligned.m16n8k16.row.col.f32.f16.f16.f32 "
        "{%0,%1,%2,%3}, {%4,%5,%6,%7}, {%8,%9}, {%0,%1,%2,%3};"
        : "+f"(d[0]), "+f"(d[1]), "+f"(d[2]), "+f"(d[3])
        : "r"(a0), "r"(a1), "r"(a2), "r"(a3), "r"(b0), "r"(b1));
}
static __device__ __forceinline__ void cpa16(uint32_t saddr, uint64_t gaddr) {
    asm volatile("cp.async.ca.shared.global [%0], [%1], 16;" :: "r"(saddr), "l"(gaddr) : "memory");
}
#define CP_COMMIT() asm volatile("cp.async.commit_group;" ::: "memory")
#define CP_WAIT(n)  asm volatile("cp.async.wait_group %0;" :: "n"(n) : "memory")

// load one 8KB chunk: 2 x 16B per thread (256 threads), one commit group
static __device__ __forceinline__ void load_chunk(uint32_t sdst, uint64_t gsrc, int tid) {
    cpa16(sdst + tid * 32,      gsrc + (size_t)tid * 32);
    cpa16(sdst + tid * 32 + 16, gsrc + (size_t)tid * 32 + 16);
    CP_COMMIT();
}

// ---------------- weight pre-conversion: fp32 -> fp16 pair-interleaved chunk image ------
__global__ void preconv_kernel(const float* __restrict__ Wz, const float* __restrict__ Wr,
                               const float* __restrict__ Wh) {
    int gid = blockIdx.x * THREADS + threadIdx.x;
    if (gid >= 3 * NCH * CHW) return;
    int w = gid / (NCH * CHW);
    int rem = gid - w * (NCH * CHW);
    int c = rem >> 11;            // / 2048
    int widx = rem & 2047;
    int n = widx >> 3;
    int p = widx & 7;
    int j = (p >> 1) + ((p & 1) << 2);
    int k = c * 16 + 2 * j;
    const float* W = (w == 0) ? Wz : (w == 1) ? Wr : Wh;
    wscratch[gid] = h2pack(W[(size_t)n * CAT + k], W[(size_t)n * CAT + k + 1]);
}

// ---------------- one K=384 GEMM pass: CTA tile 64x256, warp tile 32x64 -----------------
static __device__ __forceinline__ void gemm_pass(
    const uint32_t* Asu, const uint32_t* Bsu, uint32_t bs_byte,
    const uint32_t* wbase, float (&acc)[2][8][4],
    int m0, int n0, int lane, int tid)
{
    #pragma unroll
    for (int mt = 0; mt < 2; mt++)
        #pragma unroll
        for (int nt = 0; nt < 8; nt++)
            #pragma unroll
            for (int q = 0; q < 4; q++) acc[mt][nt][q] = 0.f;

    uint64_t g0 = gptr(wbase);
    load_chunk(bs_byte,           g0,               tid);
    load_chunk(bs_byte + CHB,     g0 + CHB,         tid);
    load_chunk(bs_byte + 2 * CHB, g0 + 2 * (size_t)CHB, tid);

    const int rq = lane >> 2;       // 0..7
    const int kq = lane & 3;        // 0..3

    #pragma unroll 1
    for (int c = 0; c < NCH; c++) {
        if (c <= NCH - 3)      CP_WAIT(2);
        else if (c == NCH - 2) CP_WAIT(1);
        else                   CP_WAIT(0);
        __syncthreads();
        if (c + 3 < NCH)
            load_chunk(bs_byte + ((c + 3) & 3) * CHB, g0 + (size_t)(c + 3) * CHB, tid);

        const uint32_t* B = Bsu + (c & 3) * CHW;
        // B fragments: one LDS.64 per nt -> (b0, b1)
        uint32_t bf[8][2];
        #pragma unroll
        for (int nt = 0; nt < 8; nt++) {
            int n = n0 + nt * 8 + rq;
            uint2 v = *reinterpret_cast<const uint2*>(B + n * 8 + 2 * kq);
            bf[nt][0] = v.x; bf[nt][1] = v.y;
        }
        const int co = c * 8 + 2 * kq;
        #pragma unroll
        for (int mt = 0; mt < 2; mt++) {
            int r = m0 + mt * 16 + rq;
            int xr = (r & 3) << 3;                  // (r+8)&3 == r&3
            uint2 lo = *reinterpret_cast<const uint2*>(Asu + r * AROWW + (co ^ xr));
            uint2 hi = *reinterpret_cast<const uint2*>(Asu + (r + 8) * AROWW + (co ^ xr));
            #pragma unroll
            for (int nt = 0; nt < 8; nt++)
                mma16(acc[mt][nt], lo.x, hi.x, lo.y, hi.y, bf[nt][0], bf[nt][1]);
        }
    }
}

// ---------------- fused GRU kernel ------------------------------------------------------
__global__ void __launch_bounds__(THREADS, 2) gru_main_kernel(
    const float* __restrict__ x, const float* __restrict__ hp,
    const float* __restrict__ bz, const float* __restrict__ br,
    const float* __restrict__ bh, float* __restrict__ out)
{
    extern __shared__ uint32_t sm[];
    uint32_t* Asu = sm;                       // 64*192 words (fp16 ih, interleave+swizzle)
    uint32_t* Bsu = sm + TM * AROWW;          // STAGES * 2048 words (B ring)
    const uint32_t bs_byte = smem_u32(Bsu);

    const int tid  = threadIdx.x;
    const int lane = tid & 31;
    const int warp = tid >> 5;
    const int m0   = (warp >> 2) * 32;
    const int n0   = (warp & 3) * 64;
    const int blockRow = blockIdx.x * TM;

    // ---- fill A smem: fp16(ih); thread handles one 16-k group per iter ----
    #pragma unroll 1
    for (int it = 0; it < 6; it++) {
        int idx = it * THREADS + tid;          // 0 .. 1535 groups
        int row = idx / 24;
        int g   = idx - row * 24;
        int k0  = g * 16;
        const float* src = (k0 < INP) ? (x + (size_t)(blockRow + row) * INP + k0)
                                      : (hp + (size_t)(blockRow + row) * HID + (k0 - INP));
        float4 v0 = *reinterpret_cast<const float4*>(src);       // k0..k3
        float4 v1 = *reinterpret_cast<const float4*>(src + 4);   // k4..k7
        float4 v2 = *reinterpret_cast<const float4*>(src + 8);   // k8..k11
        float4 v3 = *reinterpret_cast<const float4*>(src + 12);  // k12..k15
        uint4 u0, u1;   // pos p -> j = (p>>1)+(p&1)*4
        u0.x = h2pack(v0.x, v0.y);  // j0: k0,k1
        u0.y = h2pack(v2.x, v2.y);  // j4: k8,k9
        u0.z = h2pack(v0.z, v0.w);  // j1: k2,k3
        u0.w = h2pack(v2.z, v2.w);  // j5: k10,k11
        u1.x = h2pack(v1.x, v1.y);  // j2: k4,k5
        u1.y = h2pack(v3.x, v3.y);  // j6: k12,k13
        u1.z = h2pack(v1.z, v1.w);  // j3: k6,k7
        u1.w = h2pack(v3.z, v3.w);  // j7: k14,k15
        int base = row * AROWW + ((g * 8) ^ ((row & 3) << 3));
        *reinterpret_cast<uint4*>(Asu + base)     = u0;
        *reinterpret_cast<uint4*>(Asu + base + 4) = u1;
    }
    __syncthreads();

    float acc[2][8][4];

    // ================= pass 1: z = hardsigmoid(ih @ Wz^T + bz) -> out (scratch) =========
    gemm_pass(Asu, Bsu, bs_byte, wscratch, acc, m0, n0, lane, tid);
    #pragma unroll
    for (int mt = 0; mt < 2; mt++) {
        int rl = m0 + mt * 16 + (lane >> 2);
        #pragma unroll
        for (int nt = 0; nt < 8; nt++) {
            int cb = n0 + nt * 8 + ((lane & 3) << 1);
            float2 bv = *reinterpret_cast<const float2*>(bz + cb);
            float z0 = __saturatef((acc[mt][nt][0] + bv.x) * 0.16666667f + 0.5f);
            float z1 = __saturatef((acc[mt][nt][1] + bv.y) * 0.16666667f + 0.5f);
            float z2 = __saturatef((acc[mt][nt][2] + bv.x) * 0.16666667f + 0.5f);
            float z3 = __saturatef((acc[mt][nt][3] + bv.y) * 0.16666667f + 0.5f);
            size_t o0 = (size_t)(blockRow + rl) * HID + cb;
            size_t o1 = (size_t)(blockRow + rl + 8) * HID + cb;
            *reinterpret_cast<float2*>(out + o0) = make_float2(z0, z1);
            *reinterpret_cast<float2*>(out + o1) = make_float2(z2, z3);
        }
    }

    // ================= pass 2: r = hardsigmoid(ih @ Wr^T + br); A_h := fp16(r * h) ======
    gemm_pass(Asu, Bsu, bs_byte, wscratch + NCH * CHW, acc, m0, n0, lane, tid);
    __syncthreads();   // all warps done reading A (laggards may still be on chunk 23)
    #pragma unroll
    for (int mt = 0; mt < 2; mt++) {
        int rl = m0 + mt * 16 + (lane >> 2);
        int xr = (rl & 3) << 3;
        #pragma unroll
        for (int nt = 0; nt < 8; nt++) {
            int cb = n0 + nt * 8 + ((lane & 3) << 1);
            float2 bv = *reinterpret_cast<const float2*>(br + cb);
            float r0 = __saturatef((acc[mt][nt][0] + bv.x) * 0.16666667f + 0.5f);
            float r1 = __saturatef((acc[mt][nt][1] + bv.y) * 0.16666667f + 0.5f);
            float r2 = __saturatef((acc[mt][nt][2] + bv.x) * 0.16666667f + 0.5f);
            float r3 = __saturatef((acc[mt][nt][3] + bv.y) * 0.16666667f + 0.5f);
            float2 h0 = *reinterpret_cast<const float2*>(hp + (size_t)(blockRow + rl) * HID + cb);
            float2 h1 = *reinterpret_cast<const float2*>(hp + (size_t)(blockRow + rl + 8) * HID + cb);
            int kk = INP + cb;
            int g  = kk >> 4;
            int jj = (kk >> 1) & 7;
            int p  = (jj < 4) ? (jj << 1) : (((jj - 4) << 1) | 1);
            int wo = (g * 8 + p) ^ xr;           // (rl+8)&3 == rl&3
            Asu[rl * AROWW + wo]       = h2pack(r0 * h0.x, r1 * h0.y);
            Asu[(rl + 8) * AROWW + wo] = h2pack(r2 * h1.x, r3 * h1.y);
        }
    }
    __syncthreads();

    // ================= pass 3: htilde; h_next = z*h + (1-z)*hardtanh(.) =================
    gemm_pass(Asu, Bsu, bs_byte, wscratch + 2 * NCH * CHW, acc, m0, n0, lane, tid);
    #pragma unroll
    for (int mt = 0; mt < 2; mt++) {
        int rl = m0 + mt * 16 + (lane >> 2);
        #pragma unroll
        for (int nt = 0; nt < 8; nt++) {
            int cb = n0 + nt * 8 + ((lane & 3) << 1);
            float2 bv = *reinterpret_cast<const float2*>(bh + cb);
            size_t o0 = (size_t)(blockRow + rl) * HID + cb;
            size_t o1 = (size_t)(blockRow + rl + 8) * HID + cb;
            float2 zz0 = *reinterpret_cast<const float2*>(out + o0);  // z written by this thread
            float2 zz1 = *reinterpret_cast<const float2*>(out + o1);
            float2 hh0 = *reinterpret_cast<const float2*>(hp + o0);
            float2 hh1 = *reinterpret_cast<const float2*>(hp + o1);
            float t0 = fminf(fmaxf(acc[mt][nt][0] + bv.x, -1.f), 1.f);
            float t1 = fminf(fmaxf(acc[mt][nt][1] + bv.y, -1.f), 1.f);
            float t2 = fminf(fmaxf(acc[mt][nt][2] + bv.x, -1.f), 1.f);
            float t3 = fminf(fmaxf(acc[mt][nt][3] + bv.y, -1.f), 1.f);
            float2 r0, r1;
            r0.x = zz0.x * hh0.x + (1.f - zz0.x) * t0;
            r0.y = zz0.y * hh0.y + (1.f - zz0.y) * t1;
            r1.x = zz1.x * hh1.x + (1.f - zz1.x) * t2;
            r1.y = zz1.y * hh1.y + (1.f - zz1.y) * t3;
            *reinterpret_cast<float2*>(out + o0) = r0;
            *reinterpret_cast<float2*>(out + o1) = r1;
        }
    }
}

extern "C" void kernel_launch(void* const* d_in, const int* in_sizes, int n_in,
                              void* d_out, int out_size) {
    const float* x  = (const float*)d_in[0];
    const float* hp = (const float*)d_in[1];
    const float* Wz = (const float*)d_in[2];
    const float* bz = (const float*)d_in[3];
    const float* Wr = (const float*)d_in[4];
    const float* br = (const float*)d_in[5];
    const float* Wh = (const float*)d_in[6];
    const float* bh = (const float*)d_in[7];
    float* out = (float*)d_out;

    preconv_kernel<<<(3 * NCH * CHW + THREADS - 1) / THREADS, THREADS>>>(Wz, Wr, Wh);

    int batch = in_sizes[0] / INP;
    int grid = batch / TM;
    size_t smem = (size_t)(TM * AROWW + STAGES * CHW) * 4;   // 81920 B
    cudaFuncSetAttribute(gru_main_kernel,
                         cudaFuncAttributeMaxDynamicSharedMemorySize, (int)smem);
    gru_main_kernel<<<grid, THREADS, smem>>>(x, hp, bz, br, bh, out);
}

// round 7
// speedup vs baseline: 1.8332x; 1.0286x over previous
#include <cuda_runtime.h>
#include <cuda_fp16.h>
#include <cstdint>

#define THREADS  256        // 8 warps: warp grid 2m x 4n, warp tile 32x64
#define TM       64         // batch rows per CTA
#define HID      256
#define INP      128
#define CAT      384
#define NCH      24         // K chunks of 16 (one 16-k group per chunk)
#define CHW      2048       // uint32 words per chunk (256 n x 8 words)
#define CHB      8192       // bytes per chunk
#define STAGES   8
#define AROWW    192        // words per A row (384 fp16)

// Pre-converted (fp16, pair-interleaved) weights: [Wz | Wr | Wh], each NCH*CHW words.
// word layout per (chunk c, row n): pos p (0..7) holds k-pair j = (p>>1) + (p&1)*4,
// i.e. fp16x2 of (k, k+1) with k = c*16 + 2*j.
__device__ uint32_t wscratch[3 * NCH * CHW];

static __device__ __forceinline__ uint64_t gptr(const void* p) {
    uint64_t r;
    asm("cvta.to.global.u64 %0, %1;" : "=l"(r) : "l"(p));
    return r;
}
static __device__ __forceinline__ uint32_t smem_u32(const void* p) {
    uint32_t a;
    asm("{ .reg .u64 t; cvta.to.shared.u64 t, %1; cvt.u32.u64 %0, t; }" : "=r"(a) : "l"(p));
    return a;
}
static __device__ __forceinline__ uint32_t h2pack(float a, float b) {
    __half2 h = __floats2half2_rn(a, b);
    return *reinterpret_cast<uint32_t*>(&h);
}
static __device__ __forceinline__ void mma16(float* d, uint32_t a0, uint32_t a1,
                                             uint32_t a2, uint32_t a3,
                                             uint32_t b0, uint32_t b1) {
    asm volatile(
        "mma.sync.aligned.m16n8k16.row.col.f32.f16.f16.f32 "
        "{%0,%1,%2,%3}, {%4,%5,%6,%7}, {%8,%9}, {%0,%1,%2,%3};"
        : "+f"(d[0]), "+f"(d[1]), "+f"(d[2]), "+f"(d[3])
        : "r"(a0), "r"(a1), "r"(a2), "r"(a3), "r"(b0), "r"(b1));
}
static __device__ __forceinline__ void cpa16(uint32_t saddr, uint64_t gaddr) {
    asm volatile("cp.async.ca.shared.global [%0], [%1], 16;" :: "r"(saddr), "l"(gaddr) : "memory");
}
#define CP_COMMIT() asm volatile("cp.async.commit_group;" ::: "memory")
#define CP_WAIT(n)  asm volatile("cp.async.wait_group %0;" :: "n"(n) : "memory")

// load one 8KB chunk: 2 x 16B per thread (256 threads), one commit group
static __device__ __forceinline__ void load_chunk(uint32_t sdst, uint64_t gsrc, int tid) {
    cpa16(sdst + tid * 32,      gsrc + (size_t)tid * 32);
    cpa16(sdst + tid * 32 + 16, gsrc + (size_t)tid * 32 + 16);
    CP_COMMIT();
}

// ---------------- weight pre-conversion: fp32 -> fp16 pair-interleaved chunk image ------
__global__ void preconv_kernel(const float* __restrict__ Wz, const float* __restrict__ Wr,
                               const float* __restrict__ Wh) {
    int gid = blockIdx.x * THREADS + threadIdx.x;
    if (gid >= 3 * NCH * CHW) return;
    int w = gid / (NCH * CHW);
    int rem = gid - w * (NCH * CHW);
    int c = rem >> 11;            // / 2048
    int widx = rem & 2047;
    int n = widx >> 3;
    int p = widx & 7;
    int j = (p >> 1) + ((p & 1) << 2);
    int k = c * 16 + 2 * j;
    const float* W = (w == 0) ? Wz : (w == 1) ? Wr : Wh;
    wscratch[gid] = h2pack(W[(size_t)n * CAT + k], W[(size_t)n * CAT + k + 1]);
}

// compute one chunk: slot is compile-time, c = base + u
static __device__ __forceinline__ void compute_chunk(
    const uint32_t* __restrict__ Asu, const uint32_t* __restrict__ B,
    float (&acc)[2][8][4], int c, int m0, int n0, int rq, int kq)
{
    uint32_t bf[8][2];
    #pragma unroll
    for (int nt = 0; nt < 8; nt++) {
        int n = n0 + nt * 8 + rq;
        uint2 v = *reinterpret_cast<const uint2*>(B + n * 8 + 2 * kq);
        bf[nt][0] = v.x; bf[nt][1] = v.y;
    }
    const int co = c * 8 + 2 * kq;
    #pragma unroll
    for (int mt = 0; mt < 2; mt++) {
        int r = m0 + mt * 16 + rq;
        int xr = (r & 3) << 3;                  // (r+8)&3 == r&3
        uint2 lo = *reinterpret_cast<const uint2*>(Asu + r * AROWW + (co ^ xr));
        uint2 hi = *reinterpret_cast<const uint2*>(Asu + (r + 8) * AROWW + (co ^ xr));
        #pragma unroll
        for (int nt = 0; nt < 8; nt++)
            mma16(acc[mt][nt], lo.x, hi.x, lo.y, hi.y, bf[nt][0], bf[nt][1]);
    }
}

// ---------------- one K=384 GEMM pass: CTA tile 64x256, warp tile 32x64 -----------------
// 8-stage ring, 6-chunk lookahead, one __syncthreads per 2 chunks.
static __device__ __forceinline__ void gemm_pass(
    const uint32_t* Asu, const uint32_t* Bsu, uint32_t bs_byte,
    const uint32_t* wbase, float (&acc)[2][8][4],
    int m0, int n0, int lane, int tid)
{
    #pragma unroll
    for (int mt = 0; mt < 2; mt++)
        #pragma unroll
        for (int nt = 0; nt < 8; nt++)
            #pragma unroll
            for (int q = 0; q < 4; q++) acc[mt][nt][q] = 0.f;

    uint64_t g0 = gptr(wbase);
    #pragma unroll
    for (int s = 0; s < 6; s++)
        load_chunk(bs_byte + s * CHB, g0 + (size_t)s * CHB, tid);

    const int rq = lane >> 2;       // 0..7
    const int kq = lane & 3;        // 0..3

    #pragma unroll 1
    for (int cc = 0; cc < 3; cc++) {
        int base = cc * 8;
        #pragma unroll
        for (int u = 0; u < 8; u += 2) {
            CP_WAIT(4);             // chunks base+u, base+u+1 resident
            __syncthreads();
            int c6 = base + u + 6, c7 = base + u + 7;
            if (c6 < NCH) load_chunk(bs_byte + ((u + 6) & 7) * CHB, g0 + (size_t)c6 * CHB, tid);
            else          CP_COMMIT();   // empty group keeps accounting uniform
            if (c7 < NCH) load_chunk(bs_byte + ((u + 7) & 7) * CHB, g0 + (size_t)c7 * CHB, tid);
            else          CP_COMMIT();
            compute_chunk(Asu, Bsu + u * CHW,       acc, base + u,     m0, n0, rq, kq);
            compute_chunk(Asu, Bsu + (u + 1) * CHW, acc, base + u + 1, m0, n0, rq, kq);
        }
    }
}

// ---------------- fused GRU kernel ------------------------------------------------------
__global__ void __launch_bounds__(THREADS, 2) gru_main_kernel(
    const float* __restrict__ x, const float* __restrict__ hp,
    const float* __restrict__ bz, const float* __restrict__ br,
    const float* __restrict__ bh, float* __restrict__ out)
{
    extern __shared__ uint32_t sm[];
    uint32_t* Asu = sm;                       // 64*192 words (fp16 ih, interleave+swizzle)
    uint32_t* Bsu = sm + TM * AROWW;          // STAGES * 2048 words (B ring)
    const uint32_t bs_byte = smem_u32(Bsu);

    const int tid  = threadIdx.x;
    const int lane = tid & 31;
    const int warp = tid >> 5;
    const int m0   = (warp >> 2) * 32;
    const int n0   = (warp & 3) * 64;
    const int blockRow = blockIdx.x * TM;

    // ---- fill A smem: fp16(ih); thread handles one 16-k group per iter ----
    #pragma unroll 1
    for (int it = 0; it < 6; it++) {
        int idx = it * THREADS + tid;          // 0 .. 1535 groups
        int row = idx / 24;
        int g   = idx - row * 24;
        int k0  = g * 16;
        const float* src = (k0 < INP) ? (x + (size_t)(blockRow + row) * INP + k0)
                                      : (hp + (size_t)(blockRow + row) * HID + (k0 - INP));
        float4 v0 = *reinterpret_cast<const float4*>(src);       // k0..k3
        float4 v1 = *reinterpret_cast<const float4*>(src + 4);   // k4..k7
        float4 v2 = *reinterpret_cast<const float4*>(src + 8);   // k8..k11
        float4 v3 = *reinterpret_cast<const float4*>(src + 12);  // k12..k15
        uint4 u0, u1;   // pos p -> j = (p>>1)+(p&1)*4
        u0.x = h2pack(v0.x, v0.y);  // j0: k0,k1
        u0.y = h2pack(v2.x, v2.y);  // j4: k8,k9
        u0.z = h2pack(v0.z, v0.w);  // j1: k2,k3
        u0.w = h2pack(v2.z, v2.w);  // j5: k10,k11
        u1.x = h2pack(v1.x, v1.y);  // j2: k4,k5
        u1.y = h2pack(v3.x, v3.y);  // j6: k12,k13
        u1.z = h2pack(v1.z, v1.w);  // j3: k6,k7
        u1.w = h2pack(v3.z, v3.w);  // j7: k14,k15
        int base = row * AROWW + ((g * 8) ^ ((row & 3) << 3));
        *reinterpret_cast<uint4*>(Asu + base)     = u0;
        *reinterpret_cast<uint4*>(Asu + base + 4) = u1;
    }
    __syncthreads();

    float acc[2][8][4];

    // ================= pass 1: z = hardsigmoid(ih @ Wz^T + bz) -> out (scratch) =========
    gemm_pass(Asu, Bsu, bs_byte, wscratch, acc, m0, n0, lane, tid);
    #pragma unroll
    for (int mt = 0; mt < 2; mt++) {
        int rl = m0 + mt * 16 + (lane >> 2);
        #pragma unroll
        for (int nt = 0; nt < 8; nt++) {
            int cb = n0 + nt * 8 + ((lane & 3) << 1);
            float2 bv = *reinterpret_cast<const float2*>(bz + cb);
            float z0 = __saturatef((acc[mt][nt][0] + bv.x) * 0.16666667f + 0.5f);
            float z1 = __saturatef((acc[mt][nt][1] + bv.y) * 0.16666667f + 0.5f);
            float z2 = __saturatef((acc[mt][nt][2] + bv.x) * 0.16666667f + 0.5f);
            float z3 = __saturatef((acc[mt][nt][3] + bv.y) * 0.16666667f + 0.5f);
            size_t o0 = (size_t)(blockRow + rl) * HID + cb;
            size_t o1 = (size_t)(blockRow + rl + 8) * HID + cb;
            *reinterpret_cast<float2*>(out + o0) = make_float2(z0, z1);
            *reinterpret_cast<float2*>(out + o1) = make_float2(z2, z3);
        }
    }

    // ================= pass 2: r = hardsigmoid(ih @ Wr^T + br); A_h := fp16(r * h) ======
    gemm_pass(Asu, Bsu, bs_byte, wscratch + NCH * CHW, acc, m0, n0, lane, tid);
    __syncthreads();   // all warps done reading A
    #pragma unroll
    for (int mt = 0; mt < 2; mt++) {
        int rl = m0 + mt * 16 + (lane >> 2);
        int xr = (rl & 3) << 3;
        #pragma unroll
        for (int nt = 0; nt < 8; nt++) {
            int cb = n0 + nt * 8 + ((lane & 3) << 1);
            float2 bv = *reinterpret_cast<const float2*>(br + cb);
            float r0 = __saturatef((acc[mt][nt][0] + bv.x) * 0.16666667f + 0.5f);
            float r1 = __saturatef((acc[mt][nt][1] + bv.y) * 0.16666667f + 0.5f);
            float r2 = __saturatef((acc[mt][nt][2] + bv.x) * 0.16666667f + 0.5f);
            float r3 = __saturatef((acc[mt][nt][3] + bv.y) * 0.16666667f + 0.5f);
            float2 h0 = *reinterpret_cast<const float2*>(hp + (size_t)(blockRow + rl) * HID + cb);
            float2 h1 = *reinterpret_cast<const float2*>(hp + (size_t)(blockRow + rl + 8) * HID + cb);
            int kk = INP + cb;
            int g  = kk >> 4;
            int jj = (kk >> 1) & 7;
            int p  = (jj < 4) ? (jj << 1) : (((jj - 4) << 1) | 1);
            int wo = (g * 8 + p) ^ xr;           // (rl+8)&3 == rl&3
            Asu[rl * AROWW + wo]       = h2pack(r0 * h0.x, r1 * h0.y);
            Asu[(rl + 8) * AROWW + wo] = h2pack(r2 * h1.x, r3 * h1.y);
        }
    }
    __syncthreads();

    // ================= pass 3: htilde; h_next = z*h + (1-z)*hardtanh(.) =================
    gemm_pass(Asu, Bsu, bs_byte, wscratch + 2 * NCH * CHW, acc, m0, n0, lane, tid);
    #pragma unroll
    for (int mt = 0; mt < 2; mt++) {
        int rl = m0 + mt * 16 + (lane >> 2);
        #pragma unroll
        for (int nt = 0; nt < 8; nt++) {
            int cb = n0 + nt * 8 + ((lane & 3) << 1);
            float2 bv = *reinterpret_cast<const float2*>(bh + cb);
            size_t o0 = (size_t)(blockRow + rl) * HID + cb;
            size_t o1 = (size_t)(blockRow + rl + 8) * HID + cb;
            float2 zz0 = *reinterpret_cast<const float2*>(out + o0);  // z written by this thread
            float2 zz1 = *reinterpret_cast<const float2*>(out + o1);
            float2 hh0 = *reinterpret_cast<const float2*>(hp + o0);
            float2 hh1 = *reinterpret_cast<const float2*>(hp + o1);
            float t0 = fminf(fmaxf(acc[mt][nt][0] + bv.x, -1.f), 1.f);
            float t1 = fminf(fmaxf(acc[mt][nt][1] + bv.y, -1.f), 1.f);
            float t2 = fminf(fmaxf(acc[mt][nt][2] + bv.x, -1.f), 1.f);
            float t3 = fminf(fmaxf(acc[mt][nt][3] + bv.y, -1.f), 1.f);
            float2 r0, r1;
            r0.x = zz0.x * hh0.x + (1.f - zz0.x) * t0;
            r0.y = zz0.y * hh0.y + (1.f - zz0.y) * t1;
            r1.x = zz1.x * hh1.x + (1.f - zz1.x) * t2;
            r1.y = zz1.y * hh1.y + (1.f - zz1.y) * t3;
            *reinterpret_cast<float2*>(out + o0) = r0;
            *reinterpret_cast<float2*>(out + o1) = r1;
        }
    }
}

extern "C" void kernel_launch(void* const* d_in, const int* in_sizes, int n_in,
                              void* d_out, int out_size) {
    const float* x  = (const float*)d_in[0];
    const float* hp = (const float*)d_in[1];
    const float* Wz = (const float*)d_in[2];
    const float* bz = (const float*)d_in[3];
    const float* Wr = (const float*)d_in[4];
    const float* br = (const float*)d_in[5];
    const float* Wh = (const float*)d_in[6];
    const float* bh = (const float*)d_in[7];
    float* out = (float*)d_out;

    preconv_kernel<<<(3 * NCH * CHW + THREADS - 1) / THREADS, THREADS>>>(Wz, Wr, Wh);

    int batch = in_sizes[0] / INP;
    int grid = batch / TM;
    size_t smem = (size_t)(TM * AROWW + STAGES * CHW) * 4;   // 114688 B = 112 KB
    cudaFuncSetAttribute(gru_main_kernel,
                         cudaFuncAttributeMaxDynamicSharedMemorySize, (int)smem);
    gru_main_kernel<<<grid, THREADS, smem>>>(x, hp, bz, br, bh, out);
}

// round 8
// speedup vs baseline: 1.9731x; 1.0763x over previous
#include <cuda_runtime.h>
#include <cuda_fp16.h>
#include <cstdint>

#define THREADS  512        // 16 warps: warp grid 4m x 4n, warp tile 32x64
#define PTHREADS 256
#define TM       128        // batch rows per CTA
#define HID      256
#define INP      128
#define CAT      384
#define NCH      24         // K chunks of 16
#define CHW      2048       // uint32 words per chunk (256 n x 8 words)
#define AROWW    192        // words per A row (384 fp16)

// Pre-converted (fp16, pair-interleaved) weights: [Wz | Wr | Wh], each NCH*CHW words.
// word layout per (chunk c, row n): pos p (0..7) holds k-pair j = (p>>1) + (p&1)*4,
// i.e. fp16x2 of (k, k+1) with k = c*16 + 2*j.
__device__ uint32_t wscratch[3 * NCH * CHW];

static __device__ __forceinline__ uint32_t h2pack(float a, float b) {
    __half2 h = __floats2half2_rn(a, b);
    return *reinterpret_cast<uint32_t*>(&h);
}
static __device__ __forceinline__ void mma16(float* d, uint32_t a0, uint32_t a1,
                                             uint32_t a2, uint32_t a3,
                                             uint32_t b0, uint32_t b1) {
    asm volatile(
        "mma.sync.aligned.m16n8k16.row.col.f32.f16.f16.f32 "
        "{%0,%1,%2,%3}, {%4,%5,%6,%7}, {%8,%9}, {%0,%1,%2,%3};"
        : "+f"(d[0]), "+f"(d[1]), "+f"(d[2]), "+f"(d[3])
        : "r"(a0), "r"(a1), "r"(a2), "r"(a3), "r"(b0), "r"(b1));
}

// ---------------- weight pre-conversion: fp32 -> fp16 pair-interleaved chunk image ------
__global__ void preconv_kernel(const float* __restrict__ Wz, const float* __restrict__ Wr,
                               const float* __restrict__ Wh) {
    int gid = blockIdx.x * PTHREADS + threadIdx.x;
    if (gid >= 3 * NCH * CHW) return;
    int w = gid / (NCH * CHW);
    int rem = gid - w * (NCH * CHW);
    int c = rem >> 11;            // / 2048
    int widx = rem & 2047;
    int n = widx >> 3;
    int p = widx & 7;
    int j = (p >> 1) + ((p & 1) << 2);
    int k = c * 16 + 2 * j;
    const float* W = (w == 0) ? Wz : (w == 1) ? Wr : Wh;
    wscratch[gid] = h2pack(W[(size_t)n * CAT + k], W[(size_t)n * CAT + k + 1]);
}

// compute one chunk c with B fragments bf
static __device__ __forceinline__ void compute_chunk(
    const uint32_t* __restrict__ Asu, const uint2 (&bf)[8],
    float (&acc)[2][8][4], int c, int m0, int rq, int kq)
{
    const int co = c * 8 + 2 * kq;
    #pragma unroll
    for (int mt = 0; mt < 2; mt++) {
        int r = m0 + mt * 16 + rq;
        int xr = (r & 3) << 3;                  // (r+8)&3 == r&3
        uint2 lo = *reinterpret_cast<const uint2*>(Asu + r * AROWW + (co ^ xr));
        uint2 hi = *reinterpret_cast<const uint2*>(Asu + (r + 8) * AROWW + (co ^ xr));
        #pragma unroll
        for (int nt = 0; nt < 8; nt++)
            mma16(acc[mt][nt], lo.x, hi.x, lo.y, hi.y, bf[nt].x, bf[nt].y);
    }
}

// ---------------- one K=384 GEMM pass: CTA tile 128x256, warp tile 32x64 ----------------
// B fragments come straight from global (L2/L1-resident weights), register double-buffered.
// No __syncthreads inside: A smem is read-only during the pass; warps free-run.
static __device__ __forceinline__ void gemm_pass(
    const uint32_t* __restrict__ Asu, const uint32_t* __restrict__ wbase,
    float (&acc)[2][8][4], int m0, int n0, int rq, int kq)
{
    #pragma unroll
    for (int mt = 0; mt < 2; mt++)
        #pragma unroll
        for (int nt = 0; nt < 8; nt++)
            #pragma unroll
            for (int q = 0; q < 4; q++) acc[mt][nt][q] = 0.f;

    // uint2 index for (chunk 0, n = n0+rq+nt*8, kq): word (n*8+2kq) / 2
    const uint2* __restrict__ Bg =
        reinterpret_cast<const uint2*>(wbase) + ((n0 + rq) * 4 + kq);

    uint2 bf0[8], bf1[8];
    #pragma unroll
    for (int nt = 0; nt < 8; nt++) bf0[nt] = __ldg(Bg + nt * 32);

    #pragma unroll 1
    for (int cc = 0; cc < 12; cc++) {
        int c = cc * 2;
        const uint2* B1 = Bg + (size_t)(c + 1) * 1024;
        #pragma unroll
        for (int nt = 0; nt < 8; nt++) bf1[nt] = __ldg(B1 + nt * 32);
        compute_chunk(Asu, bf0, acc, c, m0, rq, kq);
        if (cc < 11) {
            const uint2* B2 = Bg + (size_t)(c + 2) * 1024;
            #pragma unroll
            for (int nt = 0; nt < 8; nt++) bf0[nt] = __ldg(B2 + nt * 32);
        }
        compute_chunk(Asu, bf1, acc, c + 1, m0, rq, kq);
    }
}

// ---------------- fused GRU kernel ------------------------------------------------------
__global__ void __launch_bounds__(THREADS, 1) gru_main_kernel(
    const float* __restrict__ x, const float* __restrict__ hp,
    const float* __restrict__ bz, const float* __restrict__ br,
    const float* __restrict__ bh, float* __restrict__ out)
{
    extern __shared__ uint32_t Asu[];         // 128*192 words (fp16 ih, interleave+swizzle)

    const int tid  = threadIdx.x;
    const int lane = tid & 31;
    const int warp = tid >> 5;
    const int m0   = (warp >> 2) * 32;
    const int n0   = (warp & 3) * 64;
    const int rq   = lane >> 2;
    const int kq   = lane & 3;
    const int blockRow = blockIdx.x * TM;

    // ---- fill A smem: fp16(ih); thread handles one 16-k group per iter ----
    #pragma unroll 1
    for (int it = 0; it < 6; it++) {
        int idx = it * THREADS + tid;          // 0 .. 3071 groups
        int row = idx / 24;
        int g   = idx - row * 24;
        int k0  = g * 16;
        const float* src = (k0 < INP) ? (x + (size_t)(blockRow + row) * INP + k0)
                                      : (hp + (size_t)(blockRow + row) * HID + (k0 - INP));
        float4 v0 = *reinterpret_cast<const float4*>(src);       // k0..k3
        float4 v1 = *reinterpret_cast<const float4*>(src + 4);   // k4..k7
        float4 v2 = *reinterpret_cast<const float4*>(src + 8);   // k8..k11
        float4 v3 = *reinterpret_cast<const float4*>(src + 12);  // k12..k15
        uint4 u0, u1;   // pos p -> j = (p>>1)+(p&1)*4
        u0.x = h2pack(v0.x, v0.y);  // j0: k0,k1
        u0.y = h2pack(v2.x, v2.y);  // j4: k8,k9
        u0.z = h2pack(v0.z, v0.w);  // j1: k2,k3
        u0.w = h2pack(v2.z, v2.w);  // j5: k10,k11
        u1.x = h2pack(v1.x, v1.y);  // j2: k4,k5
        u1.y = h2pack(v3.x, v3.y);  // j6: k12,k13
        u1.z = h2pack(v1.z, v1.w);  // j3: k6,k7
        u1.w = h2pack(v3.z, v3.w);  // j7: k14,k15
        int base = row * AROWW + ((g * 8) ^ ((row & 3) << 3));
        *reinterpret_cast<uint4*>(Asu + base)     = u0;
        *reinterpret_cast<uint4*>(Asu + base + 4) = u1;
    }
    __syncthreads();

    float acc[2][8][4];

    // ================= pass 1: z = hardsigmoid(ih @ Wz^T + bz) -> out (scratch) =========
    gemm_pass(Asu, wscratch, acc, m0, n0, rq, kq);
    #pragma unroll
    for (int mt = 0; mt < 2; mt++) {
        int rl = m0 + mt * 16 + rq;
        #pragma unroll
        for (int nt = 0; nt < 8; nt++) {
            int cb = n0 + nt * 8 + (kq << 1);
            float2 bv = *reinterpret_cast<const float2*>(bz + cb);
            float z0 = __saturatef((acc[mt][nt][0] + bv.x) * 0.16666667f + 0.5f);
            float z1 = __saturatef((acc[mt][nt][1] + bv.y) * 0.16666667f + 0.5f);
            float z2 = __saturatef((acc[mt][nt][2] + bv.x) * 0.16666667f + 0.5f);
            float z3 = __saturatef((acc[mt][nt][3] + bv.y) * 0.16666667f + 0.5f);
            size_t o0 = (size_t)(blockRow + rl) * HID + cb;
            size_t o1 = (size_t)(blockRow + rl + 8) * HID + cb;
            *reinterpret_cast<float2*>(out + o0) = make_float2(z0, z1);
            *reinterpret_cast<float2*>(out + o1) = make_float2(z2, z3);
        }
    }

    // ================= pass 2: r = hardsigmoid(ih @ Wr^T + br); A_h := fp16(r * h) ======
    gemm_pass(Asu, wscratch + NCH * CHW, acc, m0, n0, rq, kq);
    __syncthreads();   // all warps done reading A
    #pragma unroll
    for (int mt = 0; mt < 2; mt++) {
        int rl = m0 + mt * 16 + rq;
        int xr = (rl & 3) << 3;
        #pragma unroll
        for (int nt = 0; nt < 8; nt++) {
            int cb = n0 + nt * 8 + (kq << 1);
            float2 bv = *reinterpret_cast<const float2*>(br + cb);
            float r0 = __saturatef((acc[mt][nt][0] + bv.x) * 0.16666667f + 0.5f);
            float r1 = __saturatef((acc[mt][nt][1] + bv.y) * 0.16666667f + 0.5f);
            float r2 = __saturatef((acc[mt][nt][2] + bv.x) * 0.16666667f + 0.5f);
            float r3 = __saturatef((acc[mt][nt][3] + bv.y) * 0.16666667f + 0.5f);
            float2 h0 = *reinterpret_cast<const float2*>(hp + (size_t)(blockRow + rl) * HID + cb);
            float2 h1 = *reinterpret_cast<const float2*>(hp + (size_t)(blockRow + rl + 8) * HID + cb);
            int kk = INP + cb;
            int g  = kk >> 4;
            int jj = (kk >> 1) & 7;
            int p  = (jj < 4) ? (jj << 1) : (((jj - 4) << 1) | 1);
            int wo = (g * 8 + p) ^ xr;           // (rl+8)&3 == rl&3
            Asu[rl * AROWW + wo]       = h2pack(r0 * h0.x, r1 * h0.y);
            Asu[(rl + 8) * AROWW + wo] = h2pack(r2 * h1.x, r3 * h1.y);
        }
    }
    __syncthreads();

    // ================= pass 3: htilde; h_next = z*h + (1-z)*hardtanh(.) =================
    gemm_pass(Asu, wscratch + 2 * NCH * CHW, acc, m0, n0, rq, kq);
    #pragma unroll
    for (int mt = 0; mt < 2; mt++) {
        int rl = m0 + mt * 16 + rq;
        #pragma unroll
        for (int nt = 0; nt < 8; nt++) {
            int cb = n0 + nt * 8 + (kq << 1);
            float2 bv = *reinterpret_cast<const float2*>(bh + cb);
            size_t o0 = (size_t)(blockRow + rl) * HID + cb;
            size_t o1 = (size_t)(blockRow + rl + 8) * HID + cb;
            float2 zz0 = *reinterpret_cast<const float2*>(out + o0);  // z written by this thread
            float2 zz1 = *reinterpret_cast<const float2*>(out + o1);
            float2 hh0 = *reinterpret_cast<const float2*>(hp + o0);
            float2 hh1 = *reinterpret_cast<const float2*>(hp + o1);
            float t0 = fminf(fmaxf(acc[mt][nt][0] + bv.x, -1.f), 1.f);
            float t1 = fminf(fmaxf(acc[mt][nt][1] + bv.y, -1.f), 1.f);
            float t2 = fminf(fmaxf(acc[mt][nt][2] + bv.x, -1.f), 1.f);
            float t3 = fminf(fmaxf(acc[mt][nt][3] + bv.y, -1.f), 1.f);
            float2 r0, r1;
            r0.x = zz0.x * hh0.x + (1.f - zz0.x) * t0;
            r0.y = zz0.y * hh0.y + (1.f - zz0.y) * t1;
            r1.x = zz1.x * hh1.x + (1.f - zz1.x) * t2;
            r1.y = zz1.y * hh1.y + (1.f - zz1.y) * t3;
            *reinterpret_cast<float2*>(out + o0) = r0;
            *reinterpret_cast<float2*>(out + o1) = r1;
        }
    }
}

extern "C" void kernel_launch(void* const* d_in, const int* in_sizes, int n_in,
                              void* d_out, int out_size) {
    const float* x  = (const float*)d_in[0];
    const float* hp = (const float*)d_in[1];
    const float* Wz = (const float*)d_in[2];
    const float* bz = (const float*)d_in[3];
    const float* Wr = (const float*)d_in[4];
    const float* br = (const float*)d_in[5];
    const float* Wh = (const float*)d_in[6];
    const float* bh = (const float*)d_in[7];
    float* out = (float*)d_out;

    preconv_kernel<<<(3 * NCH * CHW + PTHREADS - 1) / PTHREADS, PTHREADS>>>(Wz, Wr, Wh);

    int batch = in_sizes[0] / INP;
    int grid = batch / TM;
    size_t smem = (size_t)(TM * AROWW) * 4;   // 98304 B = 96 KB
    cudaFuncSetAttribute(gru_main_kernel,
                         cudaFuncAttributeMaxDynamicSharedMemorySize, (int)smem);
    gru_main_kernel<<<grid, THREADS, smem>>>(x, hp, bz, br, bh, out);
}

// round 9
// speedup vs baseline: 2.4202x; 1.2266x over previous
#include <cuda_runtime.h>
#include <cuda_fp16.h>
#include <cstdint>

#define THREADS  256        // 8 warps: warp grid 2m x 4n, warp tile 32x64
#define PTHREADS 256
#define TM       64         // batch rows per CTA
#define HID      256
#define INP      128
#define CAT      384
#define NCH      24         // K chunks of 16
#define CHW      2048       // uint32 words per chunk (256 n x 8 words)
#define AROWW    192        // words per A row (384 fp16)

// Pre-converted (fp16, pair-interleaved) weights: [Wz | Wr | Wh], each NCH*CHW words.
// word layout per (chunk c, row n): pos p (0..7) holds k-pair j = (p>>1) + (p&1)*4,
// i.e. fp16x2 of (k, k+1) with k = c*16 + 2*j.
__device__ uint32_t wscratch[3 * NCH * CHW];

static __device__ __forceinline__ uint32_t h2pack(float a, float b) {
    __half2 h = __floats2half2_rn(a, b);
    return *reinterpret_cast<uint32_t*>(&h);
}
static __device__ __forceinline__ void mma16(float* d, uint32_t a0, uint32_t a1,
                                             uint32_t a2, uint32_t a3,
                                             uint32_t b0, uint32_t b1) {
    asm volatile(
        "mma.sync.aligned.m16n8k16.row.col.f32.f16.f16.f32 "
        "{%0,%1,%2,%3}, {%4,%5,%6,%7}, {%8,%9}, {%0,%1,%2,%3};"
        : "+f"(d[0]), "+f"(d[1]), "+f"(d[2]), "+f"(d[3])
        : "r"(a0), "r"(a1), "r"(a2), "r"(a3), "r"(b0), "r"(b1));
}

// ---------------- weight pre-conversion: fp32 -> fp16 pair-interleaved chunk image ------
__global__ void preconv_kernel(const float* __restrict__ Wz, const float* __restrict__ Wr,
                               const float* __restrict__ Wh) {
    int gid = blockIdx.x * PTHREADS + threadIdx.x;
    if (gid >= 3 * NCH * CHW) return;
    int w = gid / (NCH * CHW);
    int rem = gid - w * (NCH * CHW);
    int c = rem >> 11;            // / 2048
    int widx = rem & 2047;
    int n = widx >> 3;
    int p = widx & 7;
    int j = (p >> 1) + ((p & 1) << 2);
    int k = c * 16 + 2 * j;
    const float* W = (w == 0) ? Wz : (w == 1) ? Wr : Wh;
    wscratch[gid] = h2pack(W[(size_t)n * CAT + k], W[(size_t)n * CAT + k + 1]);
}

// compute one chunk c with B fragments bf
static __device__ __forceinline__ void compute_chunk(
    const uint32_t* __restrict__ Asu, const uint2 (&bf)[8],
    float (&acc)[2][8][4], int c, int m0, int rq, int kq)
{
    const int co = c * 8 + 2 * kq;
    #pragma unroll
    for (int mt = 0; mt < 2; mt++) {
        int r = m0 + mt * 16 + rq;
        int xr = (r & 3) << 3;                  // (r+8)&3 == r&3
        uint2 lo = *reinterpret_cast<const uint2*>(Asu + r * AROWW + (co ^ xr));
        uint2 hi = *reinterpret_cast<const uint2*>(Asu + (r + 8) * AROWW + (co ^ xr));
        #pragma unroll
        for (int nt = 0; nt < 8; nt++)
            mma16(acc[mt][nt], lo.x, hi.x, lo.y, hi.y, bf[nt].x, bf[nt].y);
    }
}

// ---------------- one K=384 GEMM pass: CTA tile 64x256, warp tile 32x64 -----------------
// B fragments straight from global (L2/L1-resident weights), register double-buffered.
// No __syncthreads inside: A smem is read-only during the pass; warps free-run.
static __device__ __forceinline__ void gemm_pass(
    const uint32_t* __restrict__ Asu, const uint32_t* __restrict__ wbase,
    float (&acc)[2][8][4], int m0, int n0, int rq, int kq)
{
    #pragma unroll
    for (int mt = 0; mt < 2; mt++)
        #pragma unroll
        for (int nt = 0; nt < 8; nt++)
            #pragma unroll
            for (int q = 0; q < 4; q++) acc[mt][nt][q] = 0.f;

    // uint2 index for (chunk 0, n = n0+rq+nt*8, kq): word (n*8+2kq) / 2
    const uint2* __restrict__ Bg =
        reinterpret_cast<const uint2*>(wbase) + ((n0 + rq) * 4 + kq);

    uint2 bf0[8], bf1[8];
    #pragma unroll
    for (int nt = 0; nt < 8; nt++) bf0[nt] = __ldg(Bg + nt * 32);

    #pragma unroll 1
    for (int cc = 0; cc < 12; cc++) {
        int c = cc * 2;
        const uint2* B1 = Bg + (size_t)(c + 1) * 1024;
        #pragma unroll
        for (int nt = 0; nt < 8; nt++) bf1[nt] = __ldg(B1 + nt * 32);
        compute_chunk(Asu, bf0, acc, c, m0, rq, kq);
        if (cc < 11) {
            const uint2* B2 = Bg + (size_t)(c + 2) * 1024;
            #pragma unroll
            for (int nt = 0; nt < 8; nt++) bf0[nt] = __ldg(B2 + nt * 32);
        }
        compute_chunk(Asu, bf1, acc, c + 1, m0, rq, kq);
    }
}

// ---------------- fused GRU kernel ------------------------------------------------------
__global__ void __launch_bounds__(THREADS, 2) gru_main_kernel(
    const float* __restrict__ x, const float* __restrict__ hp,
    const float* __restrict__ bz, const float* __restrict__ br,
    const float* __restrict__ bh, float* __restrict__ out)
{
    extern __shared__ uint32_t Asu[];         // 64*192 words (fp16 ih, interleave+swizzle)

    const int tid  = threadIdx.x;
    const int lane = tid & 31;
    const int warp = tid >> 5;
    const int m0   = (warp >> 2) * 32;
    const int n0   = (warp & 3) * 64;
    const int rq   = lane >> 2;
    const int kq   = lane & 3;
    const int blockRow = blockIdx.x * TM;

    // ---- fill A smem: fp16(ih); thread handles one 16-k group per iter ----
    #pragma unroll 1
    for (int it = 0; it < 6; it++) {
        int idx = it * THREADS + tid;          // 0 .. 1535 groups
        int row = idx / 24;
        int g   = idx - row * 24;
        int k0  = g * 16;
        const float* src = (k0 < INP) ? (x + (size_t)(blockRow + row) * INP + k0)
                                      : (hp + (size_t)(blockRow + row) * HID + (k0 - INP));
        float4 v0 = *reinterpret_cast<const float4*>(src);       // k0..k3
        float4 v1 = *reinterpret_cast<const float4*>(src + 4);   // k4..k7
        float4 v2 = *reinterpret_cast<const float4*>(src + 8);   // k8..k11
        float4 v3 = *reinterpret_cast<const float4*>(src + 12);  // k12..k15
        uint4 u0, u1;   // pos p -> j = (p>>1)+(p&1)*4
        u0.x = h2pack(v0.x, v0.y);  // j0: k0,k1
        u0.y = h2pack(v2.x, v2.y);  // j4: k8,k9
        u0.z = h2pack(v0.z, v0.w);  // j1: k2,k3
        u0.w = h2pack(v2.z, v2.w);  // j5: k10,k11
        u1.x = h2pack(v1.x, v1.y);  // j2: k4,k5
        u1.y = h2pack(v3.x, v3.y);  // j6: k12,k13
        u1.z = h2pack(v1.z, v1.w);  // j3: k6,k7
        u1.w = h2pack(v3.z, v3.w);  // j7: k14,k15
        int base = row * AROWW + ((g * 8) ^ ((row & 3) << 3));
        *reinterpret_cast<uint4*>(Asu + base)     = u0;
        *reinterpret_cast<uint4*>(Asu + base + 4) = u1;
    }
    __syncthreads();

    float acc[2][8][4];

    // ================= pass 1: z = hardsigmoid(ih @ Wz^T + bz) -> out (scratch) =========
    gemm_pass(Asu, wscratch, acc, m0, n0, rq, kq);
    #pragma unroll
    for (int mt = 0; mt < 2; mt++) {
        int rl = m0 + mt * 16 + rq;
        #pragma unroll
        for (int nt = 0; nt < 8; nt++) {
            int cb = n0 + nt * 8 + (kq << 1);
            float2 bv = *reinterpret_cast<const float2*>(bz + cb);
            float z0 = __saturatef((acc[mt][nt][0] + bv.x) * 0.16666667f + 0.5f);
            float z1 = __saturatef((acc[mt][nt][1] + bv.y) * 0.16666667f + 0.5f);
            float z2 = __saturatef((acc[mt][nt][2] + bv.x) * 0.16666667f + 0.5f);
            float z3 = __saturatef((acc[mt][nt][3] + bv.y) * 0.16666667f + 0.5f);
            size_t o0 = (size_t)(blockRow + rl) * HID + cb;
            size_t o1 = (size_t)(blockRow + rl + 8) * HID + cb;
            *reinterpret_cast<float2*>(out + o0) = make_float2(z0, z1);
            *reinterpret_cast<float2*>(out + o1) = make_float2(z2, z3);
        }
    }

    // ================= pass 2: r = hardsigmoid(ih @ Wr^T + br); A_h := fp16(r * h) ======
    gemm_pass(Asu, wscratch + NCH * CHW, acc, m0, n0, rq, kq);
    __syncthreads();   // all warps done reading A
    #pragma unroll
    for (int mt = 0; mt < 2; mt++) {
        int rl = m0 + mt * 16 + rq;
        int xr = (rl & 3) << 3;
        #pragma unroll
        for (int nt = 0; nt < 8; nt++) {
            int cb = n0 + nt * 8 + (kq << 1);
            float2 bv = *reinterpret_cast<const float2*>(br + cb);
            float r0 = __saturatef((acc[mt][nt][0] + bv.x) * 0.16666667f + 0.5f);
            float r1 = __saturatef((acc[mt][nt][1] + bv.y) * 0.16666667f + 0.5f);
            float r2 = __saturatef((acc[mt][nt][2] + bv.x) * 0.16666667f + 0.5f);
            float r3 = __saturatef((acc[mt][nt][3] + bv.y) * 0.16666667f + 0.5f);
            float2 h0 = *reinterpret_cast<const float2*>(hp + (size_t)(blockRow + rl) * HID + cb);
            float2 h1 = *reinterpret_cast<const float2*>(hp + (size_t)(blockRow + rl + 8) * HID + cb);
            int kk = INP + cb;
            int g  = kk >> 4;
            int jj = (kk >> 1) & 7;
            int p  = (jj < 4) ? (jj << 1) : (((jj - 4) << 1) | 1);
            int wo = (g * 8 + p) ^ xr;           // (rl+8)&3 == rl&3
            Asu[rl * AROWW + wo]       = h2pack(r0 * h0.x, r1 * h0.y);
            Asu[(rl + 8) * AROWW + wo] = h2pack(r2 * h1.x, r3 * h1.y);
        }
    }
    __syncthreads();

    // ================= pass 3: htilde; h_next = z*h + (1-z)*hardtanh(.) =================
    gemm_pass(Asu, wscratch + 2 * NCH * CHW, acc, m0, n0, rq, kq);
    #pragma unroll
    for (int mt = 0; mt < 2; mt++) {
        int rl = m0 + mt * 16 + rq;
        #pragma unroll
        for (int nt = 0; nt < 8; nt++) {
            int cb = n0 + nt * 8 + (kq << 1);
            float2 bv = *reinterpret_cast<const float2*>(bh + cb);
            size_t o0 = (size_t)(blockRow + rl) * HID + cb;
            size_t o1 = (size_t)(blockRow + rl + 8) * HID + cb;
            float2 zz0 = *reinterpret_cast<const float2*>(out + o0);  // z written by this thread
            float2 zz1 = *reinterpret_cast<const float2*>(out + o1);
            float2 hh0 = *reinterpret_cast<const float2*>(hp + o0);
            float2 hh1 = *reinterpret_cast<const float2*>(hp + o1);
            float t0 = fminf(fmaxf(acc[mt][nt][0] + bv.x, -1.f), 1.f);
            float t1 = fminf(fmaxf(acc[mt][nt][1] + bv.y, -1.f), 1.f);
            float t2 = fminf(fmaxf(acc[mt][nt][2] + bv.x, -1.f), 1.f);
            float t3 = fminf(fmaxf(acc[mt][nt][3] + bv.y, -1.f), 1.f);
            float2 r0, r1;
            r0.x = zz0.x * hh0.x + (1.f - zz0.x) * t0;
            r0.y = zz0.y * hh0.y + (1.f - zz0.y) * t1;
            r1.x = zz1.x * hh1.x + (1.f - zz1.x) * t2;
            r1.y = zz1.y * hh1.y + (1.f - zz1.y) * t3;
            *reinterpret_cast<float2*>(out + o0) = r0;
            *reinterpret_cast<float2*>(out + o1) = r1;
        }
    }
}

extern "C" void kernel_launch(void* const* d_in, const int* in_sizes, int n_in,
                              void* d_out, int out_size) {
    const float* x  = (const float*)d_in[0];
    const float* hp = (const float*)d_in[1];
    const float* Wz = (const float*)d_in[2];
    const float* bz = (const float*)d_in[3];
    const float* Wr = (const float*)d_in[4];
    const float* br = (const float*)d_in[5];
    const float* Wh = (const float*)d_in[6];
    const float* bh = (const float*)d_in[7];
    float* out = (float*)d_out;

    preconv_kernel<<<(3 * NCH * CHW + PTHREADS - 1) / PTHREADS, PTHREADS>>>(Wz, Wr, Wh);

    int batch = in_sizes[0] / INP;
    int grid = batch / TM;
    size_t smem = (size_t)(TM * AROWW) * 4;   // 49152 B = 48 KB
    cudaFuncSetAttribute(gru_main_kernel,
                         cudaFuncAttributeMaxDynamicSharedMemorySize, (int)smem);
    gru_main_kernel<<<grid, THREADS, smem>>>(x, hp, bz, br, bh, out);
}

// round 10
// speedup vs baseline: 2.5937x; 1.0717x over previous
#include <cuda_runtime.h>
#include <cuda_fp16.h>
#include <cstdint>

#define THREADS  256        // 8 warps: warp grid 1m x 8n, warp tile 64x32
#define PTHREADS 256
#define TM       64         // batch rows per CTA
#define HID      256
#define INP      128
#define CAT      384
#define NCH      24         // K chunks of 16
#define CHW      2048       // uint32 words per chunk (256 n x 8 words)
#define AROWW    192        // words per A row (384 fp16)

// Pre-converted (fp16, pair-interleaved) weights: [Wz | Wr | Wh], each NCH*CHW words.
// word layout per (chunk c, row n): pos p (0..7) holds k-pair j = (p>>1) + (p&1)*4,
// i.e. fp16x2 of (k, k+1) with k = c*16 + 2*j.
__device__ uint32_t wscratch[3 * NCH * CHW];

static __device__ __forceinline__ uint32_t h2pack(float a, float b) {
    __half2 h = __floats2half2_rn(a, b);
    return *reinterpret_cast<uint32_t*>(&h);
}
static __device__ __forceinline__ void mma16(float* d, uint32_t a0, uint32_t a1,
                                             uint32_t a2, uint32_t a3,
                                             uint32_t b0, uint32_t b1) {
    asm volatile(
        "mma.sync.aligned.m16n8k16.row.col.f32.f16.f16.f32 "
        "{%0,%1,%2,%3}, {%4,%5,%6,%7}, {%8,%9}, {%0,%1,%2,%3};"
        : "+f"(d[0]), "+f"(d[1]), "+f"(d[2]), "+f"(d[3])
        : "r"(a0), "r"(a1), "r"(a2), "r"(a3), "r"(b0), "r"(b1));
}

// ---------------- weight pre-conversion: fp32 -> fp16 pair-interleaved chunk image ------
__global__ void preconv_kernel(const float* __restrict__ Wz, const float* __restrict__ Wr,
                               const float* __restrict__ Wh) {
    int gid = blockIdx.x * PTHREADS + threadIdx.x;
    if (gid >= 3 * NCH * CHW) return;
    int w = gid / (NCH * CHW);
    int rem = gid - w * (NCH * CHW);
    int c = rem >> 11;            // / 2048
    int widx = rem & 2047;
    int n = widx >> 3;
    int p = widx & 7;
    int j = (p >> 1) + ((p & 1) << 2);
    int k = c * 16 + 2 * j;
    const float* W = (w == 0) ? Wz : (w == 1) ? Wr : Wh;
    wscratch[gid] = h2pack(W[(size_t)n * CAT + k], W[(size_t)n * CAT + k + 1]);
}

// load the 4 B fragments (warp tile n-width 32) for one chunk
static __device__ __forceinline__ void ldb(uint2 (&bf)[4], const uint2* __restrict__ p) {
    #pragma unroll
    for (int nt = 0; nt < 4; nt++) bf[nt] = __ldg(p + nt * 32);
}

// compute one chunk c with B fragments bf
static __device__ __forceinline__ void compute_chunk(
    const uint32_t* __restrict__ Asu, const uint2 (&bf)[4],
    float (&acc)[4][4][4], int c, int rq, int kq)
{
    const int co = c * 8 + 2 * kq;
    #pragma unroll
    for (int mt = 0; mt < 4; mt++) {
        int r = mt * 16 + rq;
        int xr = (r & 3) << 3;                  // (r+8)&3 == r&3
        uint2 lo = *reinterpret_cast<const uint2*>(Asu + r * AROWW + (co ^ xr));
        uint2 hi = *reinterpret_cast<const uint2*>(Asu + (r + 8) * AROWW + (co ^ xr));
        #pragma unroll
        for (int nt = 0; nt < 4; nt++)
            mma16(acc[mt][nt], lo.x, hi.x, lo.y, hi.y, bf[nt].x, bf[nt].y);
    }
}

// ---------------- one K=384 GEMM pass: CTA tile 64x256, warp tile 64x32 -----------------
// B straight from global (L2/L1-resident weights), 3 register buffers, distance-2 prefetch.
// No __syncthreads inside: A smem is read-only during the pass; warps free-run.
static __device__ __forceinline__ void gemm_pass(
    const uint32_t* __restrict__ Asu, const uint32_t* __restrict__ wbase,
    float (&acc)[4][4][4], int n0, int rq, int kq)
{
    #pragma unroll
    for (int mt = 0; mt < 4; mt++)
        #pragma unroll
        for (int nt = 0; nt < 4; nt++)
            #pragma unroll
            for (int q = 0; q < 4; q++) acc[mt][nt][q] = 0.f;

    // uint2 index for (chunk 0, n = n0+rq+nt*8, kq): word (n*8+2kq) / 2
    const uint2* __restrict__ Bg =
        reinterpret_cast<const uint2*>(wbase) + ((n0 + rq) * 4 + kq);

    uint2 b0[4], b1[4], b2[4];
    ldb(b0, Bg);
    ldb(b1, Bg + 1024);

    #pragma unroll 1
    for (int cc = 0; cc < 8; cc++) {
        int c = cc * 3;
        if (c + 2 < NCH) ldb(b2, Bg + (size_t)(c + 2) * 1024);
        compute_chunk(Asu, b0, acc, c, rq, kq);
        if (c + 3 < NCH) ldb(b0, Bg + (size_t)(c + 3) * 1024);
        compute_chunk(Asu, b1, acc, c + 1, rq, kq);
        if (c + 4 < NCH) ldb(b1, Bg + (size_t)(c + 4) * 1024);
        compute_chunk(Asu, b2, acc, c + 2, rq, kq);
    }
}

// ---------------- fused GRU kernel ------------------------------------------------------
__global__ void __launch_bounds__(THREADS, 2) gru_main_kernel(
    const float* __restrict__ x, const float* __restrict__ hp,
    const float* __restrict__ bz, const float* __restrict__ br,
    const float* __restrict__ bh, float* __restrict__ out)
{
    extern __shared__ uint32_t Asu[];         // 64*192 words (fp16 ih, interleave+swizzle)

    const int tid  = threadIdx.x;
    const int lane = tid & 31;
    const int warp = tid >> 5;
    const int n0   = warp * 32;
    const int rq   = lane >> 2;
    const int kq   = lane & 3;
    const int blockRow = blockIdx.x * TM;

    // ---- fill A smem: fp16(ih); thread handles one 16-k group per iter ----
    #pragma unroll 1
    for (int it = 0; it < 6; it++) {
        int idx = it * THREADS + tid;          // 0 .. 1535 groups
        int row = idx / 24;
        int g   = idx - row * 24;
        int k0  = g * 16;
        const float* src = (k0 < INP) ? (x + (size_t)(blockRow + row) * INP + k0)
                                      : (hp + (size_t)(blockRow + row) * HID + (k0 - INP));
        float4 v0 = *reinterpret_cast<const float4*>(src);       // k0..k3
        float4 v1 = *reinterpret_cast<const float4*>(src + 4);   // k4..k7
        float4 v2 = *reinterpret_cast<const float4*>(src + 8);   // k8..k11
        float4 v3 = *reinterpret_cast<const float4*>(src + 12);  // k12..k15
        uint4 u0, u1;   // pos p -> j = (p>>1)+(p&1)*4
        u0.x = h2pack(v0.x, v0.y);  // j0: k0,k1
        u0.y = h2pack(v2.x, v2.y);  // j4: k8,k9
        u0.z = h2pack(v0.z, v0.w);  // j1: k2,k3
        u0.w = h2pack(v2.z, v2.w);  // j5: k10,k11
        u1.x = h2pack(v1.x, v1.y);  // j2: k4,k5
        u1.y = h2pack(v3.x, v3.y);  // j6: k12,k13
        u1.z = h2pack(v1.z, v1.w);  // j3: k6,k7
        u1.w = h2pack(v3.z, v3.w);  // j7: k14,k15
        int base = row * AROWW + ((g * 8) ^ ((row & 3) << 3));
        *reinterpret_cast<uint4*>(Asu + base)     = u0;
        *reinterpret_cast<uint4*>(Asu + base + 4) = u1;
    }
    __syncthreads();

    float acc[4][4][4];

    // ================= pass 1: z = hardsigmoid(ih @ Wz^T + bz) -> out (scratch) =========
    gemm_pass(Asu, wscratch, acc, n0, rq, kq);
    #pragma unroll
    for (int mt = 0; mt < 4; mt++) {
        int rl = mt * 16 + rq;
        #pragma unroll
        for (int nt = 0; nt < 4; nt++) {
            int cb = n0 + nt * 8 + (kq << 1);
            float2 bv = *reinterpret_cast<const float2*>(bz + cb);
            float z0 = __saturatef((acc[mt][nt][0] + bv.x) * 0.16666667f + 0.5f);
            float z1 = __saturatef((acc[mt][nt][1] + bv.y) * 0.16666667f + 0.5f);
            float z2 = __saturatef((acc[mt][nt][2] + bv.x) * 0.16666667f + 0.5f);
            float z3 = __saturatef((acc[mt][nt][3] + bv.y) * 0.16666667f + 0.5f);
            size_t o0 = (size_t)(blockRow + rl) * HID + cb;
            size_t o1 = (size_t)(blockRow + rl + 8) * HID + cb;
            *reinterpret_cast<float2*>(out + o0) = make_float2(z0, z1);
            *reinterpret_cast<float2*>(out + o1) = make_float2(z2, z3);
        }
    }

    // ================= pass 2: r = hardsigmoid(ih @ Wr^T + br); A_h := fp16(r * h) ======
    gemm_pass(Asu, wscratch + NCH * CHW, acc, n0, rq, kq);
    __syncthreads();   // all warps done reading A
    #pragma unroll
    for (int mt = 0; mt < 4; mt++) {
        int rl = mt * 16 + rq;
        int xr = (rl & 3) << 3;
        #pragma unroll
        for (int nt = 0; nt < 4; nt++) {
            int cb = n0 + nt * 8 + (kq << 1);
            float2 bv = *reinterpret_cast<const float2*>(br + cb);
            float r0 = __saturatef((acc[mt][nt][0] + bv.x) * 0.16666667f + 0.5f);
            float r1 = __saturatef((acc[mt][nt][1] + bv.y) * 0.16666667f + 0.5f);
            float r2 = __saturatef((acc[mt][nt][2] + bv.x) * 0.16666667f + 0.5f);
            float r3 = __saturatef((acc[mt][nt][3] + bv.y) * 0.16666667f + 0.5f);
            float2 h0 = *reinterpret_cast<const float2*>(hp + (size_t)(blockRow + rl) * HID + cb);
            float2 h1 = *reinterpret_cast<const float2*>(hp + (size_t)(blockRow + rl + 8) * HID + cb);
            int kk = INP + cb;
            int g  = kk >> 4;
            int jj = (kk >> 1) & 7;
            int p  = (jj < 4) ? (jj << 1) : (((jj - 4) << 1) | 1);
            int wo = (g * 8 + p) ^ xr;           // (rl+8)&3 == rl&3
            Asu[rl * AROWW + wo]       = h2pack(r0 * h0.x, r1 * h0.y);
            Asu[(rl + 8) * AROWW + wo] = h2pack(r2 * h1.x, r3 * h1.y);
        }
    }
    __syncthreads();

    // ================= pass 3: htilde; h_next = z*h + (1-z)*hardtanh(.) =================
    gemm_pass(Asu, wscratch + 2 * NCH * CHW, acc, n0, rq, kq);
    #pragma unroll
    for (int mt = 0; mt < 4; mt++) {
        int rl = mt * 16 + rq;
        #pragma unroll
        for (int nt = 0; nt < 4; nt++) {
            int cb = n0 + nt * 8 + (kq << 1);
            float2 bv = *reinterpret_cast<const float2*>(bh + cb);
            size_t o0 = (size_t)(blockRow + rl) * HID + cb;
            size_t o1 = (size_t)(blockRow + rl + 8) * HID + cb;
            float2 zz0 = *reinterpret_cast<const float2*>(out + o0);  // z written by this thread
            float2 zz1 = *reinterpret_cast<const float2*>(out + o1);
            float2 hh0 = *reinterpret_cast<const float2*>(hp + o0);
            float2 hh1 = *reinterpret_cast<const float2*>(hp + o1);
            float t0 = fminf(fmaxf(acc[mt][nt][0] + bv.x, -1.f), 1.f);
            float t1 = fminf(fmaxf(acc[mt][nt][1] + bv.y, -1.f), 1.f);
            float t2 = fminf(fmaxf(acc[mt][nt][2] + bv.x, -1.f), 1.f);
            float t3 = fminf(fmaxf(acc[mt][nt][3] + bv.y, -1.f), 1.f);
            float2 r0, r1;
            r0.x = zz0.x * hh0.x + (1.f - zz0.x) * t0;
            r0.y = zz0.y * hh0.y + (1.f - zz0.y) * t1;
            r1.x = zz1.x * hh1.x + (1.f - zz1.x) * t2;
            r1.y = zz1.y * hh1.y + (1.f - zz1.y) * t3;
            *reinterpret_cast<float2*>(out + o0) = r0;
            *reinterpret_cast<float2*>(out + o1) = r1;
        }
    }
}

extern "C" void kernel_launch(void* const* d_in, const int* in_sizes, int n_in,
                              void* d_out, int out_size) {
    const float* x  = (const float*)d_in[0];
    const float* hp = (const float*)d_in[1];
    const float* Wz = (const float*)d_in[2];
    const float* bz = (const float*)d_in[3];
    const float* Wr = (const float*)d_in[4];
    const float* br = (const float*)d_in[5];
    const float* Wh = (const float*)d_in[6];
    const float* bh = (const float*)d_in[7];
    float* out = (float*)d_out;

    preconv_kernel<<<(3 * NCH * CHW + PTHREADS - 1) / PTHREADS, PTHREADS>>>(Wz, Wr, Wh);

    int batch = in_sizes[0] / INP;
    int grid = batch / TM;
    size_t smem = (size_t)(TM * AROWW) * 4;   // 49152 B = 48 KB
    cudaFuncSetAttribute(gru_main_kernel,
                         cudaFuncAttributeMaxDynamicSharedMemorySize, (int)smem);
    gru_main_kernel<<<grid, THREADS, smem>>>(x, hp, bz, br, bh, out);
}

// round 11
// speedup vs baseline: 2.7665x; 1.0666x over previous
#include <cuda_runtime.h>
#include <cuda_fp16.h>
#include <cstdint>

#define THREADS  256        // 8 warps: warp grid 1m x 8n, warp tile 64x32
#define PTHREADS 256
#define TM       64         // batch rows per CTA
#define HID      256
#define INP      128
#define CAT      384
#define NCH      24         // K chunks of 16
#define CHW      2048       // uint32 words per chunk (256 n x 8 words)
#define AROWW    192        // words per A row (384 fp16)
#define ZROWW    128        // words per z row (256 fp16)

// Pre-converted (fp16, pair-interleaved) weights: [Wz | Wr | Wh], each NCH*CHW words.
// word layout per (chunk c, row n): pos p (0..7) holds k-pair j = (p>>1) + (p&1)*4,
// i.e. fp16x2 of (k, k+1) with k = c*16 + 2*j.
__device__ uint32_t wscratch[3 * NCH * CHW];

static __device__ __forceinline__ uint32_t h2pack(float a, float b) {
    __half2 h = __floats2half2_rn(a, b);
    return *reinterpret_cast<uint32_t*>(&h);
}
static __device__ __forceinline__ void mma16(float* d, uint32_t a0, uint32_t a1,
                                             uint32_t a2, uint32_t a3,
                                             uint32_t b0, uint32_t b1) {
    asm volatile(
        "mma.sync.aligned.m16n8k16.row.col.f32.f16.f16.f32 "
        "{%0,%1,%2,%3}, {%4,%5,%6,%7}, {%8,%9}, {%0,%1,%2,%3};"
        : "+f"(d[0]), "+f"(d[1]), "+f"(d[2]), "+f"(d[3])
        : "r"(a0), "r"(a1), "r"(a2), "r"(a3), "r"(b0), "r"(b1));
}
// z smem word offset: row rl, packed col zc (0..127), XOR swizzle keeps lanes conflict-free
static __device__ __forceinline__ int zoff(int rl, int zc) {
    return rl * ZROWW + (zc ^ ((rl & 7) << 2));
}

// ---------------- weight pre-conversion: fp32 -> fp16 pair-interleaved chunk image ------
__global__ void preconv_kernel(const float* __restrict__ Wz, const float* __restrict__ Wr,
                               const float* __restrict__ Wh) {
    int gid = blockIdx.x * PTHREADS + threadIdx.x;
    if (gid >= 3 * NCH * CHW) return;
    int w = gid / (NCH * CHW);
    int rem = gid - w * (NCH * CHW);
    int c = rem >> 11;            // / 2048
    int widx = rem & 2047;
    int n = widx >> 3;
    int p = widx & 7;
    int j = (p >> 1) + ((p & 1) << 2);
    int k = c * 16 + 2 * j;
    const float* W = (w == 0) ? Wz : (w == 1) ? Wr : Wh;
    wscratch[gid] = h2pack(W[(size_t)n * CAT + k], W[(size_t)n * CAT + k + 1]);
}

// load the 4 B fragments (warp tile n-width 32) for one chunk
static __device__ __forceinline__ void ldb(uint2 (&bf)[4], const uint2* __restrict__ p) {
    #pragma unroll
    for (int nt = 0; nt < 4; nt++) bf[nt] = __ldg(p + nt * 32);
}

// compute one chunk c with B fragments bf
static __device__ __forceinline__ void compute_chunk(
    const uint32_t* __restrict__ Asu, const uint2 (&bf)[4],
    float (&acc)[4][4][4], int c, int rq, int kq)
{
    const int co = c * 8 + 2 * kq;
    #pragma unroll
    for (int mt = 0; mt < 4; mt++) {
        int r = mt * 16 + rq;
        int xr = (r & 3) << 3;                  // (r+8)&3 == r&3
        uint2 lo = *reinterpret_cast<const uint2*>(Asu + r * AROWW + (co ^ xr));
        uint2 hi = *reinterpret_cast<const uint2*>(Asu + (r + 8) * AROWW + (co ^ xr));
        #pragma unroll
        for (int nt = 0; nt < 4; nt++)
            mma16(acc[mt][nt], lo.x, hi.x, lo.y, hi.y, bf[nt].x, bf[nt].y);
    }
}

// ---------------- one K=384 GEMM pass: CTA tile 64x256, warp tile 64x32 -----------------
// B straight from global (L2/L1-resident weights), 4 register buffers, distance-3 prefetch.
// No __syncthreads inside: A smem is read-only during the pass; warps free-run.
static __device__ __forceinline__ void gemm_pass(
    const uint32_t* __restrict__ Asu, const uint32_t* __restrict__ wbase,
    float (&acc)[4][4][4], int n0, int rq, int kq)
{
    #pragma unroll
    for (int mt = 0; mt < 4; mt++)
        #pragma unroll
        for (int nt = 0; nt < 4; nt++)
            #pragma unroll
            for (int q = 0; q < 4; q++) acc[mt][nt][q] = 0.f;

    // uint2 index for (chunk 0, n = n0+rq+nt*8, kq): word (n*8+2kq) / 2
    const uint2* __restrict__ Bg =
        reinterpret_cast<const uint2*>(wbase) + ((n0 + rq) * 4 + kq);

    uint2 b0[4], b1[4], b2[4], b3[4];
    ldb(b0, Bg);
    ldb(b1, Bg + 1024);
    ldb(b2, Bg + 2048);

    #pragma unroll 1
    for (int cc = 0; cc < 6; cc++) {
        int c = cc * 4;
        if (c + 3 < NCH) ldb(b3, Bg + (size_t)(c + 3) * 1024);
        compute_chunk(Asu, b0, acc, c, rq, kq);
        if (c + 4 < NCH) ldb(b0, Bg + (size_t)(c + 4) * 1024);
        compute_chunk(Asu, b1, acc, c + 1, rq, kq);
        if (c + 5 < NCH) ldb(b1, Bg + (size_t)(c + 5) * 1024);
        compute_chunk(Asu, b2, acc, c + 2, rq, kq);
        if (c + 6 < NCH) ldb(b2, Bg + (size_t)(c + 6) * 1024);
        compute_chunk(Asu, b3, acc, c + 3, rq, kq);
    }
}

// ---------------- fused GRU kernel ------------------------------------------------------
__global__ void __launch_bounds__(THREADS, 2) gru_main_kernel(
    const float* __restrict__ x, const float* __restrict__ hp,
    const float* __restrict__ bz, const float* __restrict__ br,
    const float* __restrict__ bh, float* __restrict__ out)
{
    extern __shared__ uint32_t Asu[];         // 64*192 words (fp16 ih, interleave+swizzle)
    uint32_t* Zsu = Asu + TM * AROWW;         // 64*128 words (fp16x2 z stash)

    const int tid  = threadIdx.x;
    const int lane = tid & 31;
    const int warp = tid >> 5;
    const int n0   = warp * 32;
    const int rq   = lane >> 2;
    const int kq   = lane & 3;
    const int blockRow = blockIdx.x * TM;

    // ---- fill A smem: fp16(ih); thread handles one 16-k group per iter ----
    #pragma unroll 1
    for (int it = 0; it < 6; it++) {
        int idx = it * THREADS + tid;          // 0 .. 1535 groups
        int row = idx / 24;
        int g   = idx - row * 24;
        int k0  = g * 16;
        const float* src = (k0 < INP) ? (x + (size_t)(blockRow + row) * INP + k0)
                                      : (hp + (size_t)(blockRow + row) * HID + (k0 - INP));
        float4 v0 = *reinterpret_cast<const float4*>(src);       // k0..k3
        float4 v1 = *reinterpret_cast<const float4*>(src + 4);   // k4..k7
        float4 v2 = *reinterpret_cast<const float4*>(src + 8);   // k8..k11
        float4 v3 = *reinterpret_cast<const float4*>(src + 12);  // k12..k15
        uint4 u0, u1;   // pos p -> j = (p>>1)+(p&1)*4
        u0.x = h2pack(v0.x, v0.y);  // j0: k0,k1
        u0.y = h2pack(v2.x, v2.y);  // j4: k8,k9
        u0.z = h2pack(v0.z, v0.w);  // j1: k2,k3
        u0.w = h2pack(v2.z, v2.w);  // j5: k10,k11
        u1.x = h2pack(v1.x, v1.y);  // j2: k4,k5
        u1.y = h2pack(v3.x, v3.y);  // j6: k12,k13
        u1.z = h2pack(v1.z, v1.w);  // j3: k6,k7
        u1.w = h2pack(v3.z, v3.w);  // j7: k14,k15
        int base = row * AROWW + ((g * 8) ^ ((row & 3) << 3));
        *reinterpret_cast<uint4*>(Asu + base)     = u0;
        *reinterpret_cast<uint4*>(Asu + base + 4) = u1;
    }
    __syncthreads();

    float acc[4][4][4];

    // ================= pass 1: z = hardsigmoid(ih @ Wz^T + bz) -> smem stash ============
    gemm_pass(Asu, wscratch, acc, n0, rq, kq);
    #pragma unroll
    for (int mt = 0; mt < 4; mt++) {
        int rl = mt * 16 + rq;
        #pragma unroll
        for (int nt = 0; nt < 4; nt++) {
            int cb = n0 + nt * 8 + (kq << 1);
            float2 bv = *reinterpret_cast<const float2*>(bz + cb);
            float z0 = __saturatef((acc[mt][nt][0] + bv.x) * 0.16666667f + 0.5f);
            float z1 = __saturatef((acc[mt][nt][1] + bv.y) * 0.16666667f + 0.5f);
            float z2 = __saturatef((acc[mt][nt][2] + bv.x) * 0.16666667f + 0.5f);
            float z3 = __saturatef((acc[mt][nt][3] + bv.y) * 0.16666667f + 0.5f);
            int zc = (cb >> 1);
            Zsu[zoff(rl, zc)]     = h2pack(z0, z1);
            Zsu[zoff(rl + 8, zc)] = h2pack(z2, z3);   // (rl+8)&7 == rl&7
        }
    }

    // ================= pass 2: r = hardsigmoid(ih @ Wr^T + br); A_h := fp16(r * h) ======
    gemm_pass(Asu, wscratch + NCH * CHW, acc, n0, rq, kq);
    __syncthreads();   // all warps done reading A
    #pragma unroll
    for (int mt = 0; mt < 4; mt++) {
        int rl = mt * 16 + rq;
        int xr = (rl & 3) << 3;
        #pragma unroll
        for (int nt = 0; nt < 4; nt++) {
            int cb = n0 + nt * 8 + (kq << 1);
            float2 bv = *reinterpret_cast<const float2*>(br + cb);
            float r0 = __saturatef((acc[mt][nt][0] + bv.x) * 0.16666667f + 0.5f);
            float r1 = __saturatef((acc[mt][nt][1] + bv.y) * 0.16666667f + 0.5f);
            float r2 = __saturatef((acc[mt][nt][2] + bv.x) * 0.16666667f + 0.5f);
            float r3 = __saturatef((acc[mt][nt][3] + bv.y) * 0.16666667f + 0.5f);
            float2 h0 = *reinterpret_cast<const float2*>(hp + (size_t)(blockRow + rl) * HID + cb);
            float2 h1 = *reinterpret_cast<const float2*>(hp + (size_t)(blockRow + rl + 8) * HID + cb);
            int kk = INP + cb;
            int g  = kk >> 4;
            int jj = (kk >> 1) & 7;
            int p  = (jj < 4) ? (jj << 1) : (((jj - 4) << 1) | 1);
            int wo = (g * 8 + p) ^ xr;           // (rl+8)&3 == rl&3
            Asu[rl * AROWW + wo]       = h2pack(r0 * h0.x, r1 * h0.y);
            Asu[(rl + 8) * AROWW + wo] = h2pack(r2 * h1.x, r3 * h1.y);
        }
    }
    __syncthreads();

    // ================= pass 3: htilde; h_next = z*h + (1-z)*hardtanh(.) =================
    gemm_pass(Asu, wscratch + 2 * NCH * CHW, acc, n0, rq, kq);
    #pragma unroll
    for (int mt = 0; mt < 4; mt++) {
        int rl = mt * 16 + rq;
        #pragma unroll
        for (int nt = 0; nt < 4; nt++) {
            int cb = n0 + nt * 8 + (kq << 1);
            float2 bv = *reinterpret_cast<const float2*>(bh + cb);
            size_t o0 = (size_t)(blockRow + rl) * HID + cb;
            size_t o1 = (size_t)(blockRow + rl + 8) * HID + cb;
            int zc = (cb >> 1);
            uint32_t zp0 = Zsu[zoff(rl, zc)];
            uint32_t zp1 = Zsu[zoff(rl + 8, zc)];
            float2 zz0 = __half22float2(*reinterpret_cast<__half2*>(&zp0));
            float2 zz1 = __half22float2(*reinterpret_cast<__half2*>(&zp1));
            float2 hh0 = *reinterpret_cast<const float2*>(hp + o0);
            float2 hh1 = *reinterpret_cast<const float2*>(hp + o1);
            float t0 = fminf(fmaxf(acc[mt][nt][0] + bv.x, -1.f), 1.f);
            float t1 = fminf(fmaxf(acc[mt][nt][1] + bv.y, -1.f), 1.f);
            float t2 = fminf(fmaxf(acc[mt][nt][2] + bv.x, -1.f), 1.f);
            float t3 = fminf(fmaxf(acc[mt][nt][3] + bv.y, -1.f), 1.f);
            float2 r0, r1;
            r0.x = zz0.x * hh0.x + (1.f - zz0.x) * t0;
            r0.y = zz0.y * hh0.y + (1.f - zz0.y) * t1;
            r1.x = zz1.x * hh1.x + (1.f - zz1.x) * t2;
            r1.y = zz1.y * hh1.y + (1.f - zz1.y) * t3;
            *reinterpret_cast<float2*>(out + o0) = r0;
            *reinterpret_cast<float2*>(out + o1) = r1;
        }
    }
}

extern "C" void kernel_launch(void* const* d_in, const int* in_sizes, int n_in,
                              void* d_out, int out_size) {
    const float* x  = (const float*)d_in[0];
    const float* hp = (const float*)d_in[1];
    const float* Wz = (const float*)d_in[2];
    const float* bz = (const float*)d_in[3];
    const float* Wr = (const float*)d_in[4];
    const float* br = (const float*)d_in[5];
    const float* Wh = (const float*)d_in[6];
    const float* bh = (const float*)d_in[7];
    float* out = (float*)d_out;

    preconv_kernel<<<(3 * NCH * CHW + PTHREADS - 1) / PTHREADS, PTHREADS>>>(Wz, Wr, Wh);

    int batch = in_sizes[0] / INP;
    int grid = batch / TM;
    size_t smem = (size_t)(TM * AROWW + TM * ZROWW) * 4;   // 81920 B = 80 KB
    cudaFuncSetAttribute(gru_main_kernel,
                         cudaFuncAttributeMaxDynamicSharedMemorySize, (int)smem);
    gru_main_kernel<<<grid, THREADS, smem>>>(x, hp, bz, br, bh, out);
}

// round 12
// speedup vs baseline: 2.9345x; 1.0607x over previous
#include <cuda_runtime.h>
#include <cuda_fp16.h>
#include <cstdint>

#define THREADS  256        // 8 warps: warp grid 1m x 8n, warp tile 64x32
#define PTHREADS 256
#define TM       64         // batch rows per CTA
#define HID      256
#define INP      128
#define CAT      384
#define NCH      24         // K chunks of 16
#define CHW      2048       // uint32 words per chunk (256 n x 8 words)
#define AROWW    192        // words per A row (384 fp16), = 48 units of 16B
#define ZROWW    128        // words per z row (256 fp16)

// Pre-converted (fp16, pair-interleaved) weights: [Wz | Wr | Wh], each NCH*CHW words.
// word layout per (chunk c, row n): pos p (0..7) holds k-pair j = (p>>1) + (p&1)*4,
// i.e. fp16x2 of (k, k+1) with k = c*16 + 2*j.
__device__ uint32_t wscratch[3 * NCH * CHW];

static __device__ __forceinline__ uint32_t smem_u32(const void* p) {
    uint32_t a;
    asm("{ .reg .u64 t; cvta.to.shared.u64 t, %1; cvt.u32.u64 %0, t; }" : "=r"(a) : "l"(p));
    return a;
}
static __device__ __forceinline__ uint32_t h2pack(float a, float b) {
    __half2 h = __floats2half2_rn(a, b);
    return *reinterpret_cast<uint32_t*>(&h);
}
static __device__ __forceinline__ void mma16(float* d, uint32_t a0, uint32_t a1,
                                             uint32_t a2, uint32_t a3,
                                             uint32_t b0, uint32_t b1) {
    asm volatile(
        "mma.sync.aligned.m16n8k16.row.col.f32.f16.f16.f32 "
        "{%0,%1,%2,%3}, {%4,%5,%6,%7}, {%8,%9}, {%0,%1,%2,%3};"
        : "+f"(d[0]), "+f"(d[1]), "+f"(d[2]), "+f"(d[3])
        : "r"(a0), "r"(a1), "r"(a2), "r"(a3), "r"(b0), "r"(b1));
}
static __device__ __forceinline__ void ldsm4(uint32_t (&a)[4], uint32_t saddr) {
    asm volatile("ldmatrix.sync.aligned.m8n8.x4.shared.b16 {%0,%1,%2,%3}, [%4];"
        : "=r"(a[0]), "=r"(a[1]), "=r"(a[2]), "=r"(a[3]) : "r"(saddr));
}
// z smem word offset: row rl, packed col zc (0..127), XOR swizzle keeps lanes conflict-free
static __device__ __forceinline__ int zoff(int rl, int zc) {
    return rl * ZROWW + (zc ^ ((rl & 7) << 2));
}

// ---------------- weight pre-conversion: fp32 -> fp16 pair-interleaved chunk image ------
__global__ void preconv_kernel(const float* __restrict__ Wz, const float* __restrict__ Wr,
                               const float* __restrict__ Wh) {
    int gid = blockIdx.x * PTHREADS + threadIdx.x;
    if (gid >= 3 * NCH * CHW) return;
    int w = gid / (NCH * CHW);
    int rem = gid - w * (NCH * CHW);
    int c = rem >> 11;            // / 2048
    int widx = rem & 2047;
    int n = widx >> 3;
    int p = widx & 7;
    int j = (p >> 1) + ((p & 1) << 2);
    int k = c * 16 + 2 * j;
    const float* W = (w == 0) ? Wz : (w == 1) ? Wr : Wh;
    wscratch[gid] = h2pack(W[(size_t)n * CAT + k], W[(size_t)n * CAT + k + 1]);
}

// load the 4 B fragments (warp tile n-width 32) for one chunk
static __device__ __forceinline__ void ldb(uint2 (&bf)[4], const uint2* __restrict__ p) {
    #pragma unroll
    for (int nt = 0; nt < 4; nt++) bf[nt] = __ldg(p + nt * 32);
}

// compute one chunk with B fragments bf; uoff = swizzled A unit byte offset for this chunk
static __device__ __forceinline__ void compute_chunk(
    const uint32_t (&rowb)[4], uint32_t uoff, const uint2 (&bf)[4],
    float (&acc)[4][4][4])
{
    #pragma unroll
    for (int mt = 0; mt < 4; mt++) {
        uint32_t a[4];
        ldsm4(a, rowb[mt] + uoff);
        #pragma unroll
        for (int nt = 0; nt < 4; nt++)
            mma16(acc[mt][nt], a[0], a[1], a[2], a[3], bf[nt].x, bf[nt].y);
    }
}

// ---------------- one K=384 GEMM pass: CTA tile 64x256, warp tile 64x32 -----------------
// A via ldmatrix.x4 (1 per mt per chunk), B straight from global, distance-3 prefetch.
// No __syncthreads inside: A smem is read-only during the pass; warps free-run.
static __device__ __forceinline__ void gemm_pass(
    const uint32_t (&rowb)[4], uint32_t usel7, const uint32_t* __restrict__ wbase,
    float (&acc)[4][4][4], int n0, int rq, int kq)
{
    #pragma unroll
    for (int mt = 0; mt < 4; mt++)
        #pragma unroll
        for (int nt = 0; nt < 4; nt++)
            #pragma unroll
            for (int q = 0; q < 4; q++) acc[mt][nt][q] = 0.f;

    // uint2 index for (chunk 0, n = n0+rq+nt*8, kq): word (n*8+2kq) / 2
    const uint2* __restrict__ Bg =
        reinterpret_cast<const uint2*>(wbase) + ((n0 + rq) * 4 + kq);

    uint2 b0[4], b1[4], b2[4], b3[4];
    ldb(b0, Bg);
    ldb(b1, Bg + 1024);
    ldb(b2, Bg + 2048);

    // usel7 = (lane>>4) | (lane&7) context: uoff(c) = (((2c + usel) ^ l7) << 4)
    const uint32_t usel = usel7 >> 8, l7 = usel7 & 7;

    #pragma unroll 1
    for (int cc = 0; cc < 6; cc++) {
        int c = cc * 4;
        if (c + 3 < NCH) ldb(b3, Bg + (size_t)(c + 3) * 1024);
        compute_chunk(rowb, (((2 * (c + 0) + usel) ^ l7) << 4), b0, acc);
        if (c + 4 < NCH) ldb(b0, Bg + (size_t)(c + 4) * 1024);
        compute_chunk(rowb, (((2 * (c + 1) + usel) ^ l7) << 4), b1, acc);
        if (c + 5 < NCH) ldb(b1, Bg + (size_t)(c + 5) * 1024);
        compute_chunk(rowb, (((2 * (c + 2) + usel) ^ l7) << 4), b2, acc);
        if (c + 6 < NCH) ldb(b2, Bg + (size_t)(c + 6) * 1024);
        compute_chunk(rowb, (((2 * (c + 3) + usel) ^ l7) << 4), b3, acc);
    }
}

// ---------------- fused GRU kernel ------------------------------------------------------
__global__ void __launch_bounds__(THREADS, 2) gru_main_kernel(
    const float* __restrict__ x, const float* __restrict__ hp,
    const float* __restrict__ bz, const float* __restrict__ br,
    const float* __restrict__ bh, float* __restrict__ out)
{
    extern __shared__ uint32_t Asu[];         // 64 rows x 48 units(16B), unit u at u^(r&7)
    uint32_t* Zsu = Asu + TM * AROWW;         // 64*128 words (fp16x2 z stash)

    const int tid  = threadIdx.x;
    const int lane = tid & 31;
    const int warp = tid >> 5;
    const int n0   = warp * 32;
    const int rq   = lane >> 2;
    const int kq   = lane & 3;
    const int blockRow = blockIdx.x * TM;

    // ---- fill A smem: fp16(ih), natural k-order within 16B units, unit-XOR swizzle ----
    #pragma unroll 1
    for (int it = 0; it < 6; it++) {
        int idx = it * THREADS + tid;          // 0 .. 1535 groups
        int row = idx / 24;
        int g   = idx - row * 24;
        int k0  = g * 16;
        const float* src = (k0 < INP) ? (x + (size_t)(blockRow + row) * INP + k0)
                                      : (hp + (size_t)(blockRow + row) * HID + (k0 - INP));
        float4 v0 = *reinterpret_cast<const float4*>(src);       // k0..k3
        float4 v1 = *reinterpret_cast<const float4*>(src + 4);   // k4..k7
        float4 v2 = *reinterpret_cast<const float4*>(src + 8);   // k8..k11
        float4 v3 = *reinterpret_cast<const float4*>(src + 12);  // k12..k15
        uint4 u0, u1;   // natural order: unit = 8 consecutive fp16
        u0.x = h2pack(v0.x, v0.y); u0.y = h2pack(v0.z, v0.w);
        u0.z = h2pack(v1.x, v1.y); u0.w = h2pack(v1.z, v1.w);
        u1.x = h2pack(v2.x, v2.y); u1.y = h2pack(v2.z, v2.w);
        u1.z = h2pack(v3.x, v3.y); u1.w = h2pack(v3.z, v3.w);
        int r7 = row & 7;
        int un = g * 2;
        *reinterpret_cast<uint4*>(Asu + row * AROWW + ((un ^ r7) << 2))       = u0;
        *reinterpret_cast<uint4*>(Asu + row * AROWW + (((un + 1) ^ r7) << 2)) = u1;
    }
    __syncthreads();

    // ldmatrix row base addresses (bytes): row = mt*16 + (lane&15); row&7 == lane&7
    uint32_t abase = smem_u32(Asu);
    uint32_t rowb[4];
    #pragma unroll
    for (int mt = 0; mt < 4; mt++)
        rowb[mt] = abase + (mt * 16 + (lane & 15)) * (AROWW * 4);
    const uint32_t usel7 = (((uint32_t)(lane >> 4) & 1) << 8) | (uint32_t)(lane & 7);

    float acc[4][4][4];

    // ================= pass 1: z = hardsigmoid(ih @ Wz^T + bz) -> smem stash ============
    gemm_pass(rowb, usel7, wscratch, acc, n0, rq, kq);
    #pragma unroll
    for (int mt = 0; mt < 4; mt++) {
        int rl = mt * 16 + rq;
        #pragma unroll
        for (int nt = 0; nt < 4; nt++) {
            int cb = n0 + nt * 8 + (kq << 1);
            float2 bv = *reinterpret_cast<const float2*>(bz + cb);
            float z0 = __saturatef((acc[mt][nt][0] + bv.x) * 0.16666667f + 0.5f);
            float z1 = __saturatef((acc[mt][nt][1] + bv.y) * 0.16666667f + 0.5f);
            float z2 = __saturatef((acc[mt][nt][2] + bv.x) * 0.16666667f + 0.5f);
            float z3 = __saturatef((acc[mt][nt][3] + bv.y) * 0.16666667f + 0.5f);
            int zc = (cb >> 1);
            Zsu[zoff(rl, zc)]     = h2pack(z0, z1);
            Zsu[zoff(rl + 8, zc)] = h2pack(z2, z3);   // (rl+8)&7 == rl&7
        }
    }

    // ================= pass 2: r = hardsigmoid(ih @ Wr^T + br); A_h := fp16(r * h) ======
    gemm_pass(rowb, usel7, wscratch + NCH * CHW, acc, n0, rq, kq);
    __syncthreads();   // all warps done reading A
    #pragma unroll
    for (int mt = 0; mt < 4; mt++) {
        int rl = mt * 16 + rq;
        int r7 = rl & 7;
        #pragma unroll
        for (int nt = 0; nt < 4; nt++) {
            int cb = n0 + nt * 8 + (kq << 1);
            float2 bv = *reinterpret_cast<const float2*>(br + cb);
            float r0 = __saturatef((acc[mt][nt][0] + bv.x) * 0.16666667f + 0.5f);
            float r1 = __saturatef((acc[mt][nt][1] + bv.y) * 0.16666667f + 0.5f);
            float r2 = __saturatef((acc[mt][nt][2] + bv.x) * 0.16666667f + 0.5f);
            float r3 = __saturatef((acc[mt][nt][3] + bv.y) * 0.16666667f + 0.5f);
            float2 h0 = *reinterpret_cast<const float2*>(hp + (size_t)(blockRow + rl) * HID + cb);
            float2 h1 = *reinterpret_cast<const float2*>(hp + (size_t)(blockRow + rl + 8) * HID + cb);
            // k = INP + cb; unit u = k>>3, word-in-unit = (k&7)>>1 = kq
            int un = (INP + n0 + nt * 8) >> 3;
            int wo = ((un ^ r7) << 2) + kq;          // (rl+8)&7 == rl&7
            Asu[rl * AROWW + wo]       = h2pack(r0 * h0.x, r1 * h0.y);
            Asu[(rl + 8) * AROWW + wo] = h2pack(r2 * h1.x, r3 * h1.y);
        }
    }
    __syncthreads();

    // ================= pass 3: htilde; h_next = z*h + (1-z)*hardtanh(.) =================
    gemm_pass(rowb, usel7, wscratch + 2 * NCH * CHW, acc, n0, rq, kq);
    #pragma unroll
    for (int mt = 0; mt < 4; mt++) {
        int rl = mt * 16 + rq;
        #pragma unroll
        for (int nt = 0; nt < 4; nt++) {
            int cb = n0 + nt * 8 + (kq << 1);
            float2 bv = *reinterpret_cast<const float2*>(bh + cb);
            size_t o0 = (size_t)(blockRow + rl) * HID + cb;
            size_t o1 = (size_t)(blockRow + rl + 8) * HID + cb;
            int zc = (cb >> 1);
            uint32_t zp0 = Zsu[zoff(rl, zc)];
            uint32_t zp1 = Zsu[zoff(rl + 8, zc)];
            float2 zz0 = __half22float2(*reinterpret_cast<__half2*>(&zp0));
            float2 zz1 = __half22float2(*reinterpret_cast<__half2*>(&zp1));
            float2 hh0 = *reinterpret_cast<const float2*>(hp + o0);
            float2 hh1 = *reinterpret_cast<const float2*>(hp + o1);
            float t0 = fminf(fmaxf(acc[mt][nt][0] + bv.x, -1.f), 1.f);
            float t1 = fminf(fmaxf(acc[mt][nt][1] + bv.y, -1.f), 1.f);
            float t2 = fminf(fmaxf(acc[mt][nt][2] + bv.x, -1.f), 1.f);
            float t3 = fminf(fmaxf(acc[mt][nt][3] + bv.y, -1.f), 1.f);
            float2 r0, r1;
            r0.x = zz0.x * hh0.x + (1.f - zz0.x) * t0;
            r0.y = zz0.y * hh0.y + (1.f - zz0.y) * t1;
            r1.x = zz1.x * hh1.x + (1.f - zz1.x) * t2;
            r1.y = zz1.y * hh1.y + (1.f - zz1.y) * t3;
            *reinterpret_cast<float2*>(out + o0) = r0;
            *reinterpret_cast<float2*>(out + o1) = r1;
        }
    }
}

extern "C" void kernel_launch(void* const* d_in, const int* in_sizes, int n_in,
                              void* d_out, int out_size) {
    const float* x  = (const float*)d_in[0];
    const float* hp = (const float*)d_in[1];
    const float* Wz = (const float*)d_in[2];
    const float* bz = (const float*)d_in[3];
    const float* Wr = (const float*)d_in[4];
    const float* br = (const float*)d_in[5];
    const float* Wh = (const float*)d_in[6];
    const float* bh = (const float*)d_in[7];
    float* out = (float*)d_out;

    preconv_kernel<<<(3 * NCH * CHW + PTHREADS - 1) / PTHREADS, PTHREADS>>>(Wz, Wr, Wh);

    int batch = in_sizes[0] / INP;
    int grid = batch / TM;
    size_t smem = (size_t)(TM * AROWW + TM * ZROWW) * 4;   // 81920 B = 80 KB
    cudaFuncSetAttribute(gru_main_kernel,
                         cudaFuncAttributeMaxDynamicSharedMemorySize, (int)smem);
    gru_main_kernel<<<grid, THREADS, smem>>>(x, hp, bz, br, bh, out);
}

// round 13
// speedup vs baseline: 2.9441x; 1.0032x over previous
#include <cuda_runtime.h>
#include <cuda_fp16.h>
#include <cstdint>

#define THREADS  256        // 8 warps: warp grid 1m x 8n, warp tile 64x32
#define PTHREADS 256
#define TM       64         // batch rows per CTA
#define HID      256
#define INP      128
#define CAT      384
#define NCH      24         // K chunks of 16
#define CHW      2048       // uint32 words per chunk (256 n x 8 words)
#define AROWW    192        // words per A row (384 fp16), = 48 units of 16B
#define ZROWW    128        // words per z row (256 fp16)

// Pre-converted (fp16, pair-interleaved) weights: [Wz | Wr | Wh], each NCH*CHW words.
// word layout per (chunk c, row n): pos p (0..7) holds k-pair j = (p>>1) + (p&1)*4,
// i.e. fp16x2 of (k, k+1) with k = c*16 + 2*j.
__device__ uint32_t wscratch[3 * NCH * CHW];

static __device__ __forceinline__ uint32_t smem_u32(const void* p) {
    uint32_t a;
    asm("{ .reg .u64 t; cvta.to.shared.u64 t, %1; cvt.u32.u64 %0, t; }" : "=r"(a) : "l"(p));
    return a;
}
static __device__ __forceinline__ uint32_t h2pack(float a, float b) {
    __half2 h = __floats2half2_rn(a, b);
    return *reinterpret_cast<uint32_t*>(&h);
}
static __device__ __forceinline__ void mma16(float* d, uint32_t a0, uint32_t a1,
                                             uint32_t a2, uint32_t a3,
                                             uint32_t b0, uint32_t b1) {
    asm volatile(
        "mma.sync.aligned.m16n8k16.row.col.f32.f16.f16.f32 "
        "{%0,%1,%2,%3}, {%4,%5,%6,%7}, {%8,%9}, {%0,%1,%2,%3};"
        : "+f"(d[0]), "+f"(d[1]), "+f"(d[2]), "+f"(d[3])
        : "r"(a0), "r"(a1), "r"(a2), "r"(a3), "r"(b0), "r"(b1));
}
static __device__ __forceinline__ void ldsm4(uint32_t (&a)[4], uint32_t saddr) {
    asm volatile("ldmatrix.sync.aligned.m8n8.x4.shared.b16 {%0,%1,%2,%3}, [%4];"
        : "=r"(a[0]), "=r"(a[1]), "=r"(a[2]), "=r"(a[3]) : "r"(saddr));
}
// z smem word offset: row rl, packed col zc (0..127), XOR swizzle keeps lanes conflict-free
static __device__ __forceinline__ int zoff(int rl, int zc) {
    return rl * ZROWW + (zc ^ ((rl & 7) << 2));
}

// ---------------- weight pre-conversion: fp32 -> fp16 pair-interleaved chunk image ------
__global__ void preconv_kernel(const float* __restrict__ Wz, const float* __restrict__ Wr,
                               const float* __restrict__ Wh) {
    int gid = blockIdx.x * PTHREADS + threadIdx.x;
    if (gid >= 3 * NCH * CHW) return;
    int w = gid / (NCH * CHW);
    int rem = gid - w * (NCH * CHW);
    int c = rem >> 11;            // / 2048
    int widx = rem & 2047;
    int n = widx >> 3;
    int p = widx & 7;
    int j = (p >> 1) + ((p & 1) << 2);
    int k = c * 16 + 2 * j;
    const float* W = (w == 0) ? Wz : (w == 1) ? Wr : Wh;
    wscratch[gid] = h2pack(W[(size_t)n * CAT + k], W[(size_t)n * CAT + k + 1]);
}

// load the 4 B fragments (warp tile n-width 32) for one chunk
static __device__ __forceinline__ void ldb(uint2 (&bf)[4], const uint2* __restrict__ p) {
    #pragma unroll
    for (int nt = 0; nt < 4; nt++) bf[nt] = __ldg(p + nt * 32);
}

// compute one chunk, A-fragment software-pipelined:
// on entry af = fragment (this chunk, mt=0); on exit af = fragment (next chunk, mt=0).
static __device__ __forceinline__ void compute_chunk(
    const uint32_t (&rowb)[4], uint32_t uoff_cur, uint32_t uoff_next,
    const uint2 (&bf)[4], float (&acc)[4][4][4], uint32_t (&af)[4])
{
    uint32_t cur[4] = {af[0], af[1], af[2], af[3]};
    #pragma unroll
    for (int mt = 0; mt < 4; mt++) {
        uint32_t nxt[4];
        if (mt < 3) ldsm4(nxt, rowb[mt + 1] + uoff_cur);
        else        ldsm4(nxt, rowb[0] + uoff_next);
        #pragma unroll
        for (int nt = 0; nt < 4; nt++)
            mma16(acc[mt][nt], cur[0], cur[1], cur[2], cur[3], bf[nt].x, bf[nt].y);
        cur[0] = nxt[0]; cur[1] = nxt[1]; cur[2] = nxt[2]; cur[3] = nxt[3];
    }
    af[0] = cur[0]; af[1] = cur[1]; af[2] = cur[2]; af[3] = cur[3];
}

#define UOFF(c) ((((2 * (c)) + usel) ^ l7) << 4)

// ---------------- one K=384 GEMM pass: CTA tile 64x256, warp tile 64x32 -----------------
// A via pipelined ldmatrix.x4, B straight from global, distance-3 prefetch.
// No __syncthreads inside: A smem is read-only during the pass; warps free-run.
static __device__ __forceinline__ void gemm_pass(
    const uint32_t (&rowb)[4], uint32_t usel7, const uint32_t* __restrict__ wbase,
    float (&acc)[4][4][4], int n0, int rq, int kq)
{
    #pragma unroll
    for (int mt = 0; mt < 4; mt++)
        #pragma unroll
        for (int nt = 0; nt < 4; nt++)
            #pragma unroll
            for (int q = 0; q < 4; q++) acc[mt][nt][q] = 0.f;

    // uint2 index for (chunk 0, n = n0+rq+nt*8, kq): word (n*8+2kq) / 2
    const uint2* __restrict__ Bg =
        reinterpret_cast<const uint2*>(wbase) + ((n0 + rq) * 4 + kq);

    const uint32_t usel = usel7 >> 8, l7 = usel7 & 7;

    uint2 b0[4], b1[4], b2[4], b3[4];
    ldb(b0, Bg);
    ldb(b1, Bg + 1024);
    ldb(b2, Bg + 2048);
    uint32_t af[4];
    ldsm4(af, rowb[0] + UOFF(0));

    #pragma unroll 1
    for (int cc = 0; cc < 6; cc++) {
        int c = cc * 4;
        if (c + 3 < NCH) ldb(b3, Bg + (size_t)(c + 3) * 1024);
        compute_chunk(rowb, UOFF(c + 0), UOFF(c + 1), b0, acc, af);
        if (c + 4 < NCH) ldb(b0, Bg + (size_t)(c + 4) * 1024);
        compute_chunk(rowb, UOFF(c + 1), UOFF(c + 2), b1, acc, af);
        if (c + 5 < NCH) ldb(b1, Bg + (size_t)(c + 5) * 1024);
        compute_chunk(rowb, UOFF(c + 2), UOFF(c + 3), b2, acc, af);
        if (c + 6 < NCH) ldb(b2, Bg + (size_t)(c + 6) * 1024);
        // tail lookahead clamped in-bounds (re-reads last chunk; value unused next pass)
        compute_chunk(rowb, UOFF(c + 3), UOFF(c + 4 < NCH ? c + 4 : NCH - 1), b3, acc, af);
    }
}

// ---------------- fused GRU kernel ------------------------------------------------------
__global__ void __launch_bounds__(THREADS, 2) gru_main_kernel(
    const float* __restrict__ x, const float* __restrict__ hp,
    const float* __restrict__ bz, const float* __restrict__ br,
    const float* __restrict__ bh, float* __restrict__ out)
{
    extern __shared__ uint32_t Asu[];         // 64 rows x 48 units(16B), unit u at u^(r&7)
    uint32_t* Zsu = Asu + TM * AROWW;         // 64*128 words (fp16x2 z stash)

    const int tid  = threadIdx.x;
    const int lane = tid & 31;
    const int warp = tid >> 5;
    const int n0   = warp * 32;
    const int rq   = lane >> 2;
    const int kq   = lane & 3;
    const int blockRow = blockIdx.x * TM;

    // ---- fill A smem: fp16(ih), natural k-order within 16B units, unit-XOR swizzle ----
    #pragma unroll 1
    for (int it = 0; it < 6; it++) {
        int idx = it * THREADS + tid;          // 0 .. 1535 groups
        int row = idx / 24;
        int g   = idx - row * 24;
        int k0  = g * 16;
        const float* src = (k0 < INP) ? (x + (size_t)(blockRow + row) * INP + k0)
                                      : (hp + (size_t)(blockRow + row) * HID + (k0 - INP));
        float4 v0 = *reinterpret_cast<const float4*>(src);       // k0..k3
        float4 v1 = *reinterpret_cast<const float4*>(src + 4);   // k4..k7
        float4 v2 = *reinterpret_cast<const float4*>(src + 8);   // k8..k11
        float4 v3 = *reinterpret_cast<const float4*>(src + 12);  // k12..k15
        uint4 u0, u1;   // natural order: unit = 8 consecutive fp16
        u0.x = h2pack(v0.x, v0.y); u0.y = h2pack(v0.z, v0.w);
        u0.z = h2pack(v1.x, v1.y); u0.w = h2pack(v1.z, v1.w);
        u1.x = h2pack(v2.x, v2.y); u1.y = h2pack(v2.z, v2.w);
        u1.z = h2pack(v3.x, v3.y); u1.w = h2pack(v3.z, v3.w);
        int r7 = row & 7;
        int un = g * 2;
        *reinterpret_cast<uint4*>(Asu + row * AROWW + ((un ^ r7) << 2))       = u0;
        *reinterpret_cast<uint4*>(Asu + row * AROWW + (((un + 1) ^ r7) << 2)) = u1;
    }
    __syncthreads();

    // ldmatrix row base addresses (bytes): row = mt*16 + (lane&15); row&7 == lane&7
    uint32_t abase = smem_u32(Asu);
    uint32_t rowb[4];
    #pragma unroll
    for (int mt = 0; mt < 4; mt++)
        rowb[mt] = abase + (mt * 16 + (lane & 15)) * (AROWW * 4);
    const uint32_t usel7 = (((uint32_t)(lane >> 4) & 1) << 8) | (uint32_t)(lane & 7);

    float acc[4][4][4];

    // ================= pass 1: z = hardsigmoid(ih @ Wz^T + bz) -> smem stash ============
    gemm_pass(rowb, usel7, wscratch, acc, n0, rq, kq);
    #pragma unroll
    for (int mt = 0; mt < 4; mt++) {
        int rl = mt * 16 + rq;
        #pragma unroll
        for (int nt = 0; nt < 4; nt++) {
            int cb = n0 + nt * 8 + (kq << 1);
            float2 bv = *reinterpret_cast<const float2*>(bz + cb);
            float z0 = __saturatef((acc[mt][nt][0] + bv.x) * 0.16666667f + 0.5f);
            float z1 = __saturatef((acc[mt][nt][1] + bv.y) * 0.16666667f + 0.5f);
            float z2 = __saturatef((acc[mt][nt][2] + bv.x) * 0.16666667f + 0.5f);
            float z3 = __saturatef((acc[mt][nt][3] + bv.y) * 0.16666667f + 0.5f);
            int zc = (cb >> 1);
            Zsu[zoff(rl, zc)]     = h2pack(z0, z1);
            Zsu[zoff(rl + 8, zc)] = h2pack(z2, z3);   // (rl+8)&7 == rl&7
        }
    }

    // ================= pass 2: r = hardsigmoid(ih @ Wr^T + br); A_h := fp16(r * h) ======
    gemm_pass(rowb, usel7, wscratch + NCH * CHW, acc, n0, rq, kq);
    __syncthreads();   // all warps done reading A
    #pragma unroll
    for (int mt = 0; mt < 4; mt++) {
        int rl = mt * 16 + rq;
        int r7 = rl & 7;
        #pragma unroll
        for (int nt = 0; nt < 4; nt++) {
            int cb = n0 + nt * 8 + (kq << 1);
            float2 bv = *reinterpret_cast<const float2*>(br + cb);
            float r0 = __saturatef((acc[mt][nt][0] + bv.x) * 0.16666667f + 0.5f);
            float r1 = __saturatef((acc[mt][nt][1] + bv.y) * 0.16666667f + 0.5f);
            float r2 = __saturatef((acc[mt][nt][2] + bv.x) * 0.16666667f + 0.5f);
            float r3 = __saturatef((acc[mt][nt][3] + bv.y) * 0.16666667f + 0.5f);
            float2 h0 = *reinterpret_cast<const float2*>(hp + (size_t)(blockRow + rl) * HID + cb);
            float2 h1 = *reinterpret_cast<const float2*>(hp + (size_t)(blockRow + rl + 8) * HID + cb);
            // k = INP + cb; unit u = k>>3, word-in-unit = (k&7)>>1 = kq
            int un = (INP + n0 + nt * 8) >> 3;
            int wo = ((un ^ r7) << 2) + kq;          // (rl+8)&7 == rl&7
            Asu[rl * AROWW + wo]       = h2pack(r0 * h0.x, r1 * h0.y);
            Asu[(rl + 8) * AROWW + wo] = h2pack(r2 * h1.x, r3 * h1.y);
        }
    }
    __syncthreads();

    // ================= pass 3: htilde; h_next = z*h + (1-z)*hardtanh(.) =================
    gemm_pass(rowb, usel7, wscratch + 2 * NCH * CHW, acc, n0, rq, kq);
    #pragma unroll
    for (int mt = 0; mt < 4; mt++) {
        int rl = mt * 16 + rq;
        #pragma unroll
        for (int nt = 0; nt < 4; nt++) {
            int cb = n0 + nt * 8 + (kq << 1);
            float2 bv = *reinterpret_cast<const float2*>(bh + cb);
            size_t o0 = (size_t)(blockRow + rl) * HID + cb;
            size_t o1 = (size_t)(blockRow + rl + 8) * HID + cb;
            int zc = (cb >> 1);
            uint32_t zp0 = Zsu[zoff(rl, zc)];
            uint32_t zp1 = Zsu[zoff(rl + 8, zc)];
            float2 zz0 = __half22float2(*reinterpret_cast<__half2*>(&zp0));
            float2 zz1 = __half22float2(*reinterpret_cast<__half2*>(&zp1));
            float2 hh0 = *reinterpret_cast<const float2*>(hp + o0);
            float2 hh1 = *reinterpret_cast<const float2*>(hp + o1);
            float t0 = fminf(fmaxf(acc[mt][nt][0] + bv.x, -1.f), 1.f);
            float t1 = fminf(fmaxf(acc[mt][nt][1] + bv.y, -1.f), 1.f);
            float t2 = fminf(fmaxf(acc[mt][nt][2] + bv.x, -1.f), 1.f);
            float t3 = fminf(fmaxf(acc[mt][nt][3] + bv.y, -1.f), 1.f);
            float2 r0, r1;
            r0.x = zz0.x * hh0.x + (1.f - zz0.x) * t0;
            r0.y = zz0.y * hh0.y + (1.f - zz0.y) * t1;
            r1.x = zz1.x * hh1.x + (1.f - zz1.x) * t2;
            r1.y = zz1.y * hh1.y + (1.f - zz1.y) * t3;
            *reinterpret_cast<float2*>(out + o0) = r0;
            *reinterpret_cast<float2*>(out + o1) = r1;
        }
    }
}

extern "C" void kernel_launch(void* const* d_in, const int* in_sizes, int n_in,
                              void* d_out, int out_size) {
    const float* x  = (const float*)d_in[0];
    const float* hp = (const float*)d_in[1];
    const float* Wz = (const float*)d_in[2];
    const float* bz = (const float*)d_in[3];
    const float* Wr = (const float*)d_in[4];
    const float* br = (const float*)d_in[5];
    const float* Wh = (const float*)d_in[6];
    const float* bh = (const float*)d_in[7];
    float* out = (float*)d_out;

    preconv_kernel<<<(3 * NCH * CHW + PTHREADS - 1) / PTHREADS, PTHREADS>>>(Wz, Wr, Wh);

    int batch = in_sizes[0] / INP;
    int grid = batch / TM;
    size_t smem = (size_t)(TM * AROWW + TM * ZROWW) * 4;   // 81920 B = 80 KB
    cudaFuncSetAttribute(gru_main_kernel,
                         cudaFuncAttributeMaxDynamicSharedMemorySize, (int)smem);
    gru_main_kernel<<<grid, THREADS, smem>>>(x, hp, bz, br, bh, out);
}

// round 14
// speedup vs baseline: 3.0682x; 1.0422x over previous
#include <cuda_runtime.h>
#include <cuda_fp16.h>
#include <cstdint>

#define THREADS  256        // 8 warps: warp grid 1m x 8n, warp tile 64x32
#define PTHREADS 256
#define TM       64         // batch rows per CTA
#define HID      256
#define INP      128
#define CAT      384
#define NCH      24         // K chunks of 16
#define CHW      2048       // uint32 words per chunk (256 n x 8 words)
#define AROWW    192        // words per A row (384 fp16), = 48 units of 16B
#define ZROWW    128        // words per z row (256 fp16)

// Pre-converted fp16 pair-interleaved weights.
// Layout: [zr fused: chunk c -> Wz at slot 2c, Wr at slot 2c+1 (48 slots)] [Wh: 24 slots]
// word layout per (slot, row n): pos p (0..7) holds k-pair j = (p>>1) + (p&1)*4.
__device__ uint32_t wscratch[3 * NCH * CHW];

static __device__ __forceinline__ uint32_t smem_u32(const void* p) {
    uint32_t a;
    asm("{ .reg .u64 t; cvta.to.shared.u64 t, %1; cvt.u32.u64 %0, t; }" : "=r"(a) : "l"(p));
    return a;
}
static __device__ __forceinline__ uint32_t h2pack(float a, float b) {
    __half2 h = __floats2half2_rn(a, b);
    return *reinterpret_cast<uint32_t*>(&h);
}
static __device__ __forceinline__ float2 h2unpack(uint32_t u) {
    return __half22float2(*reinterpret_cast<__half2*>(&u));
}
static __device__ __forceinline__ void mma16(float* d, uint32_t a0, uint32_t a1,
                                             uint32_t a2, uint32_t a3,
                                             uint32_t b0, uint32_t b1) {
    asm volatile(
        "mma.sync.aligned.m16n8k16.row.col.f32.f16.f16.f32 "
        "{%0,%1,%2,%3}, {%4,%5,%6,%7}, {%8,%9}, {%0,%1,%2,%3};"
        : "+f"(d[0]), "+f"(d[1]), "+f"(d[2]), "+f"(d[3])
        : "r"(a0), "r"(a1), "r"(a2), "r"(a3), "r"(b0), "r"(b1));
}
// fp16-accumulator variant: D/C = 2 regs (half2 pairs), same element mapping as f32 d0..d3
static __device__ __forceinline__ void mma16h(uint32_t* d, const uint32_t (&a)[4],
                                              uint32_t b0, uint32_t b1) {
    asm volatile(
        "mma.sync.aligned.m16n8k16.row.col.f16.f16.f16.f16 "
        "{%0,%1}, {%2,%3,%4,%5}, {%6,%7}, {%0,%1};"
        : "+r"(d[0]), "+r"(d[1])
        : "r"(a[0]), "r"(a[1]), "r"(a[2]), "r"(a[3]), "r"(b0), "r"(b1));
}
static __device__ __forceinline__ void ldsm4(uint32_t (&a)[4], uint32_t saddr) {
    asm volatile("ldmatrix.sync.aligned.m8n8.x4.shared.b16 {%0,%1,%2,%3}, [%4];"
        : "=r"(a[0]), "=r"(a[1]), "=r"(a[2]), "=r"(a[3]) : "r"(saddr));
}
// z smem word offset: row rl, packed col zc (0..127), XOR swizzle keeps lanes conflict-free
static __device__ __forceinline__ int zoff(int rl, int zc) {
    return rl * ZROWW + (zc ^ ((rl & 7) << 2));
}

// ---------------- weight pre-conversion: fp32 -> fp16 pair-interleaved images -----------
__global__ void preconv_kernel(const float* __restrict__ Wz, const float* __restrict__ Wr,
                               const float* __restrict__ Wh) {
    int gid = blockIdx.x * PTHREADS + threadIdx.x;
    if (gid >= 3 * NCH * CHW) return;
    int w = gid / (NCH * CHW);
    int rem = gid - w * (NCH * CHW);
    int c = rem >> 11;            // / 2048
    int widx = rem & 2047;
    int n = widx >> 3;
    int p = widx & 7;
    int j = (p >> 1) + ((p & 1) << 2);
    int k = c * 16 + 2 * j;
    const float* W = (w == 0) ? Wz : (w == 1) ? Wr : Wh;
    uint32_t val = h2pack(W[(size_t)n * CAT + k], W[(size_t)n * CAT + k + 1]);
    size_t slot = (w == 0) ? (size_t)(2 * c)
                : (w == 1) ? (size_t)(2 * c + 1)
                           : (size_t)(2 * NCH + c);
    wscratch[slot * CHW + widx] = val;
}

// load the 4 B fragments (warp tile n-width 32) for one slot
static __device__ __forceinline__ void ldb(uint2 (&bf)[4], const uint2* __restrict__ p) {
    #pragma unroll
    for (int nt = 0; nt < 4; nt++) bf[nt] = __ldg(p + nt * 32);
}

#define UOFF(c) ((((2 * (c)) + usel) ^ l7) << 4)

// fused z+r chunk: one A fragment feeds 8 mma (4 z + 4 r), fp16 accumulators
static __device__ __forceinline__ void compute_chunk_zr(
    const uint32_t (&rowb)[4], uint32_t uoff_cur, uint32_t uoff_next,
    const uint2 (&bz)[4], const uint2 (&br)[4],
    uint32_t (&accz)[4][4][2], uint32_t (&accr)[4][4][2], uint32_t (&af)[4])
{
    uint32_t cur[4] = {af[0], af[1], af[2], af[3]};
    #pragma unroll
    for (int mt = 0; mt < 4; mt++) {
        uint32_t nxt[4];
        if (mt < 3) ldsm4(nxt, rowb[mt + 1] + uoff_cur);
        else        ldsm4(nxt, rowb[0] + uoff_next);
        #pragma unroll
        for (int nt = 0; nt < 4; nt++) {
            mma16h(accz[mt][nt], cur, bz[nt].x, bz[nt].y);
            mma16h(accr[mt][nt], cur, br[nt].x, br[nt].y);
        }
        cur[0] = nxt[0]; cur[1] = nxt[1]; cur[2] = nxt[2]; cur[3] = nxt[3];
    }
    af[0] = cur[0]; af[1] = cur[1]; af[2] = cur[2]; af[3] = cur[3];
}

// ---------------- fused z+r pass: A read once per chunk for BOTH matrices ---------------
static __device__ __forceinline__ void gemm_fused_zr(
    const uint32_t (&rowb)[4], uint32_t usel7, const uint32_t* __restrict__ wbase,
    uint32_t (&accz)[4][4][2], uint32_t (&accr)[4][4][2], int n0, int rq, int kq)
{
    #pragma unroll
    for (int mt = 0; mt < 4; mt++)
        #pragma unroll
        for (int nt = 0; nt < 4; nt++) {
            accz[mt][nt][0] = 0u; accz[mt][nt][1] = 0u;
            accr[mt][nt][0] = 0u; accr[mt][nt][1] = 0u;
        }

    const uint2* __restrict__ Bg =
        reinterpret_cast<const uint2*>(wbase) + ((n0 + rq) * 4 + kq);
    const uint32_t usel = usel7 >> 8, l7 = usel7 & 7;

    uint2 bz0[4], br0[4], bz1[4], br1[4];
    ldb(bz0, Bg);                 // chunk 0: Wz slot 0
    ldb(br0, Bg + 1024);          // chunk 0: Wr slot 1
    uint32_t af[4];
    ldsm4(af, rowb[0] + UOFF(0));

    #pragma unroll 1
    for (int cc = 0; cc < 12; cc++) {
        int c = cc * 2;
        if (c + 1 < NCH) {
            ldb(bz1, Bg + (size_t)(2 * (c + 1)) * 1024);
            ldb(br1, Bg + (size_t)(2 * (c + 1) + 1) * 1024);
        }
        compute_chunk_zr(rowb, UOFF(c), UOFF(c + 1), bz0, br0, accz, accr, af);
        if (c + 2 < NCH) {
            ldb(bz0, Bg + (size_t)(2 * (c + 2)) * 1024);
            ldb(br0, Bg + (size_t)(2 * (c + 2) + 1) * 1024);
        }
        compute_chunk_zr(rowb, UOFF(c + 1), UOFF(c + 2 < NCH ? c + 2 : NCH - 1),
                         bz1, br1, accz, accr, af);
    }
}

// fp32-acc chunk (pass 3), A-fragment pipelined as R13
static __device__ __forceinline__ void compute_chunk(
    const uint32_t (&rowb)[4], uint32_t uoff_cur, uint32_t uoff_next,
    const uint2 (&bf)[4], float (&acc)[4][4][4], uint32_t (&af)[4])
{
    uint32_t cur[4] = {af[0], af[1], af[2], af[3]};
    #pragma unroll
    for (int mt = 0; mt < 4; mt++) {
        uint32_t nxt[4];
        if (mt < 3) ldsm4(nxt, rowb[mt + 1] + uoff_cur);
        else        ldsm4(nxt, rowb[0] + uoff_next);
        #pragma unroll
        for (int nt = 0; nt < 4; nt++)
            mma16(acc[mt][nt], cur[0], cur[1], cur[2], cur[3], bf[nt].x, bf[nt].y);
        cur[0] = nxt[0]; cur[1] = nxt[1]; cur[2] = nxt[2]; cur[3] = nxt[3];
    }
    af[0] = cur[0]; af[1] = cur[1]; af[2] = cur[2]; af[3] = cur[3];
}

// ---------------- pass 3 GEMM: fp32 acc, 4 B buffers, distance-3 ------------------------
static __device__ __forceinline__ void gemm_pass(
    const uint32_t (&rowb)[4], uint32_t usel7, const uint32_t* __restrict__ wbase,
    float (&acc)[4][4][4], int n0, int rq, int kq)
{
    #pragma unroll
    for (int mt = 0; mt < 4; mt++)
        #pragma unroll
        for (int nt = 0; nt < 4; nt++)
            #pragma unroll
            for (int q = 0; q < 4; q++) acc[mt][nt][q] = 0.f;

    const uint2* __restrict__ Bg =
        reinterpret_cast<const uint2*>(wbase) + ((n0 + rq) * 4 + kq);
    const uint32_t usel = usel7 >> 8, l7 = usel7 & 7;

    uint2 b0[4], b1[4], b2[4], b3[4];
    ldb(b0, Bg);
    ldb(b1, Bg + 1024);
    ldb(b2, Bg + 2048);
    uint32_t af[4];
    ldsm4(af, rowb[0] + UOFF(0));

    #pragma unroll 1
    for (int cc = 0; cc < 6; cc++) {
        int c = cc * 4;
        if (c + 3 < NCH) ldb(b3, Bg + (size_t)(c + 3) * 1024);
        compute_chunk(rowb, UOFF(c + 0), UOFF(c + 1), b0, acc, af);
        if (c + 4 < NCH) ldb(b0, Bg + (size_t)(c + 4) * 1024);
        compute_chunk(rowb, UOFF(c + 1), UOFF(c + 2), b1, acc, af);
        if (c + 5 < NCH) ldb(b1, Bg + (size_t)(c + 5) * 1024);
        compute_chunk(rowb, UOFF(c + 2), UOFF(c + 3), b2, acc, af);
        if (c + 6 < NCH) ldb(b2, Bg + (size_t)(c + 6) * 1024);
        compute_chunk(rowb, UOFF(c + 3), UOFF(c + 4 < NCH ? c + 4 : NCH - 1), b3, acc, af);
    }
}

// ---------------- fused GRU kernel ------------------------------------------------------
__global__ void __launch_bounds__(THREADS, 2) gru_main_kernel(
    const float* __restrict__ x, const float* __restrict__ hp,
    const float* __restrict__ bz, const float* __restrict__ br,
    const float* __restrict__ bh, float* __restrict__ out)
{
    extern __shared__ uint32_t Asu[];         // 64 rows x 48 units(16B), unit u at u^(r&7)
    uint32_t* Zsu = Asu + TM * AROWW;         // 64*128 words (fp16x2 z stash)

    const int tid  = threadIdx.x;
    const int lane = tid & 31;
    const int warp = tid >> 5;
    const int n0   = warp * 32;
    const int rq   = lane >> 2;
    const int kq   = lane & 3;
    const int blockRow = blockIdx.x * TM;

    // ---- fill A smem: fp16(ih), natural k-order within 16B units, unit-XOR swizzle ----
    #pragma unroll 1
    for (int it = 0; it < 6; it++) {
        int idx = it * THREADS + tid;          // 0 .. 1535 groups
        int row = idx / 24;
        int g   = idx - row * 24;
        int k0  = g * 16;
        const float* src = (k0 < INP) ? (x + (size_t)(blockRow + row) * INP + k0)
                                      : (hp + (size_t)(blockRow + row) * HID + (k0 - INP));
        float4 v0 = *reinterpret_cast<const float4*>(src);
        float4 v1 = *reinterpret_cast<const float4*>(src + 4);
        float4 v2 = *reinterpret_cast<const float4*>(src + 8);
        float4 v3 = *reinterpret_cast<const float4*>(src + 12);
        uint4 u0, u1;
        u0.x = h2pack(v0.x, v0.y); u0.y = h2pack(v0.z, v0.w);
        u0.z = h2pack(v1.x, v1.y); u0.w = h2pack(v1.z, v1.w);
        u1.x = h2pack(v2.x, v2.y); u1.y = h2pack(v2.z, v2.w);
        u1.z = h2pack(v3.x, v3.y); u1.w = h2pack(v3.z, v3.w);
        int r7 = row & 7;
        int un = g * 2;
        *reinterpret_cast<uint4*>(Asu + row * AROWW + ((un ^ r7) << 2))       = u0;
        *reinterpret_cast<uint4*>(Asu + row * AROWW + (((un + 1) ^ r7) << 2)) = u1;
    }
    __syncthreads();

    uint32_t abase = smem_u32(Asu);
    uint32_t rowb[4];
    #pragma unroll
    for (int mt = 0; mt < 4; mt++)
        rowb[mt] = abase + (mt * 16 + (lane & 15)) * (AROWW * 4);
    const uint32_t usel7 = (((uint32_t)(lane >> 4) & 1) << 8) | (uint32_t)(lane & 7);

    // ================= fused pass: z & r preacts (fp16 acc) =============================
    {
        uint32_t accz[4][4][2], accr[4][4][2];
        gemm_fused_zr(rowb, usel7, wscratch, accz, accr, n0, rq, kq);

        // z epilogue -> Zsu (no A access; no sync needed yet)
        #pragma unroll
        for (int mt = 0; mt < 4; mt++) {
            int rl = mt * 16 + rq;
            #pragma unroll
            for (int nt = 0; nt < 4; nt++) {
                int cb = n0 + nt * 8 + (kq << 1);
                float2 bv = *reinterpret_cast<const float2*>(bz + cb);
                float2 v0 = h2unpack(accz[mt][nt][0]);   // row rl,  cols cb, cb+1
                float2 v1 = h2unpack(accz[mt][nt][1]);   // row rl+8
                float z0 = __saturatef((v0.x + bv.x) * 0.16666667f + 0.5f);
                float z1 = __saturatef((v0.y + bv.y) * 0.16666667f + 0.5f);
                float z2 = __saturatef((v1.x + bv.x) * 0.16666667f + 0.5f);
                float z3 = __saturatef((v1.y + bv.y) * 0.16666667f + 0.5f);
                int zc = (cb >> 1);
                Zsu[zoff(rl, zc)]     = h2pack(z0, z1);
                Zsu[zoff(rl + 8, zc)] = h2pack(z2, z3);
            }
        }

        __syncthreads();   // all warps done reading A in fused pass

        // r epilogue: A_h := fp16(r * h)
        #pragma unroll
        for (int mt = 0; mt < 4; mt++) {
            int rl = mt * 16 + rq;
            int r7 = rl & 7;
            #pragma unroll
            for (int nt = 0; nt < 4; nt++) {
                int cb = n0 + nt * 8 + (kq << 1);
                float2 bv = *reinterpret_cast<const float2*>(br + cb);
                float2 v0 = h2unpack(accr[mt][nt][0]);
                float2 v1 = h2unpack(accr[mt][nt][1]);
                float r0 = __saturatef((v0.x + bv.x) * 0.16666667f + 0.5f);
                float r1 = __saturatef((v0.y + bv.y) * 0.16666667f + 0.5f);
                float r2 = __saturatef((v1.x + bv.x) * 0.16666667f + 0.5f);
                float r3 = __saturatef((v1.y + bv.y) * 0.16666667f + 0.5f);
                float2 h0 = *reinterpret_cast<const float2*>(hp + (size_t)(blockRow + rl) * HID + cb);
                float2 h1 = *reinterpret_cast<const float2*>(hp + (size_t)(blockRow + rl + 8) * HID + cb);
                int un = (INP + n0 + nt * 8) >> 3;
                int wo = ((un ^ r7) << 2) + kq;
                Asu[rl * AROWW + wo]       = h2pack(r0 * h0.x, r1 * h0.y);
                Asu[(rl + 8) * AROWW + wo] = h2pack(r2 * h1.x, r3 * h1.y);
            }
        }
    }
    __syncthreads();

    // ================= pass 3: htilde (fp32 acc); h_next = z*h + (1-z)*hardtanh(.) ======
    float acc[4][4][4];
    gemm_pass(rowb, usel7, wscratch + 2 * NCH * CHW, acc, n0, rq, kq);
    #pragma unroll
    for (int mt = 0; mt < 4; mt++) {
        int rl = mt * 16 + rq;
        #pragma unroll
        for (int nt = 0; nt < 4; nt++) {
            int cb = n0 + nt * 8 + (kq << 1);
            float2 bv = *reinterpret_cast<const float2*>(bh + cb);
            size_t o0 = (size_t)(blockRow + rl) * HID + cb;
            size_t o1 = (size_t)(blockRow + rl + 8) * HID + cb;
            int zc = (cb >> 1);
            float2 zz0 = h2unpack(Zsu[zoff(rl, zc)]);
            float2 zz1 = h2unpack(Zsu[zoff(rl + 8, zc)]);
            float2 hh0 = *reinterpret_cast<const float2*>(hp + o0);
            float2 hh1 = *reinterpret_cast<const float2*>(hp + o1);
            float t0 = fminf(fmaxf(acc[mt][nt][0] + bv.x, -1.f), 1.f);
            float t1 = fminf(fmaxf(acc[mt][nt][1] + bv.y, -1.f), 1.f);
            float t2 = fminf(fmaxf(acc[mt][nt][2] + bv.x, -1.f), 1.f);
            float t3 = fminf(fmaxf(acc[mt][nt][3] + bv.y, -1.f), 1.f);
            float2 r0, r1;
            r0.x = zz0.x * hh0.x + (1.f - zz0.x) * t0;
            r0.y = zz0.y * hh0.y + (1.f - zz0.y) * t1;
            r1.x = zz1.x * hh1.x + (1.f - zz1.x) * t2;
            r1.y = zz1.y * hh1.y + (1.f - zz1.y) * t3;
            *reinterpret_cast<float2*>(out + o0) = r0;
            *reinterpret_cast<float2*>(out + o1) = r1;
        }
    }
}

extern "C" void kernel_launch(void* const* d_in, const int* in_sizes, int n_in,
                              void* d_out, int out_size) {
    const float* x  = (const float*)d_in[0];
    const float* hp = (const float*)d_in[1];
    const float* Wz = (const float*)d_in[2];
    const float* bz = (const float*)d_in[3];
    const float* Wr = (const float*)d_in[4];
    const float* br = (const float*)d_in[5];
    const float* Wh = (const float*)d_in[6];
    const float* bh = (const float*)d_in[7];
    float* out = (float*)d_out;

    preconv_kernel<<<(3 * NCH * CHW + PTHREADS - 1) / PTHREADS, PTHREADS>>>(Wz, Wr, Wh);

    int batch = in_sizes[0] / INP;
    int grid = batch / TM;
    size_t smem = (size_t)(TM * AROWW + TM * ZROWW) * 4;   // 81920 B = 80 KB
    cudaFuncSetAttribute(gru_main_kernel,
                         cudaFuncAttributeMaxDynamicSharedMemorySize, (int)smem);
    gru_main_kernel<<<grid, THREADS, smem>>>(x, hp, bz, br, bh, out);
}